// round 1
// baseline (speedup 1.0000x reference)
#include <cuda_runtime.h>
#include <cstddef>

// ---------------------------------------------------------------------------
// RPNHead: for each level f in {p2..p6} (NHWC, C=256):
//   s  = relu(conv3x3(f, w_share[3,3,256,512]) + b_share)          (SAME pad)
//   cl = conv1x1(s, w_cls[1,1,512,6]) + b_cls  -> (B, H*W*3, 2), softmax last
//   bp = conv1x1(s, w_box[1,1,512,12]) + b_box -> (B, H*W*3, 4)
// Outputs concatenated over levels along position axis:
//   out = [class_logit | class_prob | box_pred] flattened in that order.
// ---------------------------------------------------------------------------

#define C_IN   256
#define C_MID  512
#define KTOT   2304      // 9 * 256
#define BM     128
#define BN     128
#define BK     16
#define BM_PAD 132
#define NCHUNK (KTOT / BK)   // 144

#define TOT_POS 261888       // 3*(256^2+128^2+64^2+32^2+16^2)

// scratch for s (max level: 2*256*256 pixels * 512 ch) = 256 MiB
__device__ float g_s[2 * 256 * 256 * 512];

__device__ __forceinline__ float4 ld4(const float* p) {
    return *reinterpret_cast<const float4*>(p);
}

// ---------------------------------------------------------------------------
// Kernel 1: conv3x3 (SAME) + bias + relu, implicit GEMM.
//   A[m][k] = x[b, h+r-1, w+s-1, ci],  m=pixel, k=(r*3+s)*256+ci (0 if OOB)
//   B[k][n] = w_share[k*512 + n]   (HWIO is already [k][co] row-major)
//   s[m][n] = relu(sum_k A*B + bias[n])
// grid: (M/128, 4), block: 256 threads, thread computes 8x8.
// ---------------------------------------------------------------------------
__global__ __launch_bounds__(256)
void conv3x3_relu_kernel(const float* __restrict__ x,
                         const float* __restrict__ wsh,
                         const float* __restrict__ bias,
                         int H, int HH)
{
    __shared__ __align__(16) float As[2][BK][BM_PAD];
    __shared__ __align__(16) float Bs[2][BK][BN];

    const int tid = threadIdx.x;
    const int m0  = blockIdx.x * BM;
    const int n0  = blockIdx.y * BN;

    // ---- A load mapping: v = tid (+256): m_local = v>>2 (0..127), k4 = v&3
    const int a_m  = tid >> 2;          // 0..63 ; second vec handles a_m+64
    const int a_k4 = tid & 3;           // 0..3  (16B within the 64B k-row)
    int bA[2], hA[2], wA[2];
#pragma unroll
    for (int i = 0; i < 2; i++) {
        int p = m0 + a_m + i * 64;
        bA[i] = p / HH; int rem = p - bA[i] * HH;
        hA[i] = rem / H; wA[i] = rem - hA[i] * H;
    }
    // ---- B load mapping: v = tid (+256): kk = v>>5 (0..7 / 8..15), n4 = v&31
    const int b_kk = tid >> 5;
    const int b_n4 = tid & 31;

    const int ty = tid >> 4;            // 0..15 -> M micro
    const int tx = tid & 15;            // 0..15 -> N micro

    float acc[8][8];
#pragma unroll
    for (int i = 0; i < 8; i++)
#pragma unroll
        for (int j = 0; j < 8; j++) acc[i][j] = 0.f;

    float4 ar[2], br[2];

    // ---- fetch chunk 0
    {
        const int c = 0;
        const int rs = c >> 4;
        const int ci = ((c & 15) << 4) + (a_k4 << 2);
        const int ro = rs / 3 - 1, so = rs % 3 - 1;
#pragma unroll
        for (int i = 0; i < 2; i++) {
            int hh = hA[i] + ro, ww = wA[i] + so;
            if ((unsigned)hh < (unsigned)H && (unsigned)ww < (unsigned)H)
                ar[i] = ld4(x + ((size_t)(bA[i] * H + hh) * H + ww) * C_IN + ci);
            else
                ar[i] = make_float4(0.f, 0.f, 0.f, 0.f);
        }
        const float* wp = wsh + (size_t)(c * BK + b_kk) * C_MID + n0 + b_n4 * 4;
        br[0] = ld4(wp);
        br[1] = ld4(wp + 8 * C_MID);
    }
    // store chunk 0 -> buf 0
    {
#pragma unroll
        for (int i = 0; i < 2; i++) {
            int m = a_m + i * 64;
            As[0][a_k4 * 4 + 0][m] = ar[i].x;
            As[0][a_k4 * 4 + 1][m] = ar[i].y;
            As[0][a_k4 * 4 + 2][m] = ar[i].z;
            As[0][a_k4 * 4 + 3][m] = ar[i].w;
        }
        *reinterpret_cast<float4*>(&Bs[0][b_kk][b_n4 * 4])     = br[0];
        *reinterpret_cast<float4*>(&Bs[0][b_kk + 8][b_n4 * 4]) = br[1];
    }
    __syncthreads();

    for (int c = 0; c < NCHUNK; c++) {
        const int cur = c & 1;
        if (c + 1 < NCHUNK) {
            const int cn = c + 1;
            const int rs = cn >> 4;
            const int ci = ((cn & 15) << 4) + (a_k4 << 2);
            const int ro = rs / 3 - 1, so = rs % 3 - 1;
#pragma unroll
            for (int i = 0; i < 2; i++) {
                int hh = hA[i] + ro, ww = wA[i] + so;
                if ((unsigned)hh < (unsigned)H && (unsigned)ww < (unsigned)H)
                    ar[i] = ld4(x + ((size_t)(bA[i] * H + hh) * H + ww) * C_IN + ci);
                else
                    ar[i] = make_float4(0.f, 0.f, 0.f, 0.f);
            }
            const float* wp = wsh + (size_t)(cn * BK + b_kk) * C_MID + n0 + b_n4 * 4;
            br[0] = ld4(wp);
            br[1] = ld4(wp + 8 * C_MID);
        }

#pragma unroll
        for (int kk = 0; kk < BK; kk++) {
            float4 a0 = *reinterpret_cast<const float4*>(&As[cur][kk][ty * 8]);
            float4 a1 = *reinterpret_cast<const float4*>(&As[cur][kk][ty * 8 + 4]);
            float4 b0 = *reinterpret_cast<const float4*>(&Bs[cur][kk][tx * 8]);
            float4 b1 = *reinterpret_cast<const float4*>(&Bs[cur][kk][tx * 8 + 4]);
            float av[8] = {a0.x, a0.y, a0.z, a0.w, a1.x, a1.y, a1.z, a1.w};
            float bv[8] = {b0.x, b0.y, b0.z, b0.w, b1.x, b1.y, b1.z, b1.w};
#pragma unroll
            for (int i = 0; i < 8; i++)
#pragma unroll
                for (int j = 0; j < 8; j++)
                    acc[i][j] += av[i] * bv[j];
        }

        if (c + 1 < NCHUNK) {
            const int nxt = cur ^ 1;
#pragma unroll
            for (int i = 0; i < 2; i++) {
                int m = a_m + i * 64;
                As[nxt][a_k4 * 4 + 0][m] = ar[i].x;
                As[nxt][a_k4 * 4 + 1][m] = ar[i].y;
                As[nxt][a_k4 * 4 + 2][m] = ar[i].z;
                As[nxt][a_k4 * 4 + 3][m] = ar[i].w;
            }
            *reinterpret_cast<float4*>(&Bs[nxt][b_kk][b_n4 * 4])     = br[0];
            *reinterpret_cast<float4*>(&Bs[nxt][b_kk + 8][b_n4 * 4]) = br[1];
            __syncthreads();
        }
    }

    // epilogue: bias + relu, write to g_s
    const int m_base = m0 + ty * 8;
    const int n_base = n0 + tx * 8;
    float bi[8];
#pragma unroll
    for (int j = 0; j < 8; j++) bi[j] = bias[n_base + j];
#pragma unroll
    for (int i = 0; i < 8; i++) {
        float* op = g_s + (size_t)(m_base + i) * C_MID + n_base;
        float v[8];
#pragma unroll
        for (int j = 0; j < 8; j++) {
            float t = acc[i][j] + bi[j];
            v[j] = t > 0.f ? t : 0.f;
        }
        *reinterpret_cast<float4*>(op)     = make_float4(v[0], v[1], v[2], v[3]);
        *reinterpret_cast<float4*>(op + 4) = make_float4(v[4], v[5], v[6], v[7]);
    }
}

// ---------------------------------------------------------------------------
// Kernel 2: 1x1 heads + softmax + scattered writes.
// warp processes 4 pixels; 18 outputs/pixel (6 cls + 12 box).
// grid: M/32 blocks of 256 threads.
// ---------------------------------------------------------------------------
#define PPW 4

__global__ __launch_bounds__(256)
void heads_kernel(const float* __restrict__ wcls, const float* __restrict__ bcls,
                  const float* __restrict__ wbox, const float* __restrict__ bbox,
                  float* __restrict__ out_logit, float* __restrict__ out_prob,
                  float* __restrict__ out_box,
                  int HH, int levelOff)
{
    __shared__ float wsm[C_MID * 18];
    __shared__ float bsm[18];

    const int tid = threadIdx.x;
    for (int i = tid; i < C_MID * 6; i += 256) {
        int c = i / 6, o = i - c * 6;
        wsm[c * 18 + o] = wcls[i];
    }
    for (int i = tid; i < C_MID * 12; i += 256) {
        int c = i / 12, o = i - c * 12;
        wsm[c * 18 + 6 + o] = wbox[i];
    }
    if (tid < 6)       bsm[tid] = bcls[tid];
    else if (tid < 18) bsm[tid] = bbox[tid - 6];
    __syncthreads();

    const int warp = blockIdx.x * 8 + (tid >> 5);
    const int lane = tid & 31;
    const int p0   = warp * PPW;

    float acc[PPW][18];
#pragma unroll
    for (int px = 0; px < PPW; px++)
#pragma unroll
        for (int o = 0; o < 18; o++) acc[px][o] = 0.f;

    const float* sp = g_s + (size_t)p0 * C_MID + lane;
#pragma unroll 4
    for (int it = 0; it < C_MID / 32; it++) {
        const int c = lane + it * 32;
        float sv[PPW];
#pragma unroll
        for (int px = 0; px < PPW; px++) sv[px] = sp[(size_t)px * C_MID + it * 32];
        const float* wr = &wsm[c * 18];
#pragma unroll
        for (int o = 0; o < 18; o++) {
            float wv = wr[o];
#pragma unroll
            for (int px = 0; px < PPW; px++) acc[px][o] += sv[px] * wv;
        }
    }

    // butterfly reduce: every lane ends with full sums
#pragma unroll
    for (int off = 16; off; off >>= 1)
#pragma unroll
        for (int px = 0; px < PPW; px++)
#pragma unroll
            for (int o = 0; o < 18; o++)
                acc[px][o] += __shfl_xor_sync(0xffffffffu, acc[px][o], off);

    if (lane < 18) {
        const int o  = lane;
        const float bo = bsm[o];
#pragma unroll
        for (int px = 0; px < PPW; px++) {
            int m = p0 + px;
            int b = m / HH; int rem = m - b * HH;     // rem = h*H + w
            if (o < 6) {
                int pair = o & ~1;
                int a    = o >> 1;
                int cls  = o & 1;
                float l0 = acc[px][pair]     + bsm[pair];
                float l1 = acc[px][pair + 1] + bsm[pair + 1];
                float lv = (cls == 0) ? l0 : l1;
                float mx = fmaxf(l0, l1);
                float e0 = expf(l0 - mx), e1 = expf(l1 - mx);
                float pr = ((cls == 0) ? e0 : e1) / (e0 + e1);
                int pos = levelOff + rem * 3 + a;
                int idx = (b * TOT_POS + pos) * 2 + cls;
                out_logit[idx] = lv;
                out_prob[idx]  = pr;
            } else {
                int oo = o - 6;
                int a = oo >> 2, coord = oo & 3;
                int pos = levelOff + rem * 3 + a;
                out_box[(b * TOT_POS + pos) * 4 + coord] = acc[px][o] + bo;
            }
        }
    }
}

// ---------------------------------------------------------------------------
// launch
// ---------------------------------------------------------------------------
extern "C" void kernel_launch(void* const* d_in, const int* in_sizes, int n_in,
                              void* d_out, int out_size)
{
    const float* p[5];
    for (int i = 0; i < 5; i++) p[i] = (const float*)d_in[i];
    const float* w_share = (const float*)d_in[5];
    const float* b_share = (const float*)d_in[6];
    const float* w_cls   = (const float*)d_in[7];
    const float* b_cls   = (const float*)d_in[8];
    const float* w_box   = (const float*)d_in[9];
    const float* b_box   = (const float*)d_in[10];

    float* out       = (float*)d_out;
    float* out_logit = out;
    float* out_prob  = out + 2 * TOT_POS * 2;          // after logits
    float* out_box   = out + 2 * (2 * TOT_POS * 2);    // after logits+probs

    const int Hs[5]   = {256, 128, 64, 32, 16};
    const int offs[5] = {0, 196608, 245760, 258048, 261120};

    for (int lvl = 0; lvl < 5; lvl++) {
        const int H  = Hs[lvl];
        const int HH = H * H;
        const int M  = 2 * HH;     // B=2

        dim3 cgrid(M / BM, C_MID / BN);
        conv3x3_relu_kernel<<<cgrid, 256>>>(p[lvl], w_share, b_share, H, HH);

        heads_kernel<<<M / 32, 256>>>(w_cls, b_cls, w_box, b_box,
                                      out_logit, out_prob, out_box,
                                      HH, offs[lvl]);
    }
}

// round 3
// speedup vs baseline: 2.1724x; 2.1724x over previous
#include <cuda_runtime.h>
#include <cuda_bf16.h>
#include <cuda_fp16.h>
#include <cstdint>
#include <cstddef>

// ============================================================================
// RPNHead via 3-split bf16 mma.sync (tripled-K GEMM) + fp16 s + fused heads.
// ============================================================================

#define TOTM     174592          // total pixels over all levels (B=2)
#define TOT_POS  261888
#define K3TOT    6912            // 3 * 9 * 256
#define NSTAGE   216             // K3TOT / 32

// smem: A/B tiles [128][40] bf16 (pad 40 for conflict-free ldmatrix)
#define TILE_B   (128 * 40 * 2)  // 10240 bytes

__device__ __align__(16) __nv_bfloat16 g_xhi[(size_t)TOTM * 256];
__device__ __align__(16) __nv_bfloat16 g_xlo[(size_t)TOTM * 256];
__device__ __align__(16) __nv_bfloat16 g_wT3[(size_t)512 * K3TOT];
__device__ __align__(16) __half        g_s16[(size_t)TOTM * 512];

// ---------------------------------------------------------------------------
__device__ __forceinline__ uint32_t smem_u32(const void* p) {
    uint32_t a;
    asm("{ .reg .u64 t; cvta.to.shared.u64 t, %1; cvt.u32.u64 %0, t; }"
        : "=r"(a) : "l"(p));
    return a;
}
__device__ __forceinline__ void cp_async16(uint32_t dst, const void* src, int sz) {
    asm volatile("cp.async.ca.shared.global [%0], [%1], 16, %2;"
                 :: "r"(dst), "l"(src), "r"(sz) : "memory");
}
__device__ __forceinline__ void cp_commit() {
    asm volatile("cp.async.commit_group;" ::: "memory");
}
__device__ __forceinline__ void cp_wait1() {
    asm volatile("cp.async.wait_group 1;" ::: "memory");
}
__device__ __forceinline__ void cp_wait0() {
    asm volatile("cp.async.wait_group 0;" ::: "memory");
}
__device__ __forceinline__ void ldm_x4(uint32_t* r, uint32_t addr) {
    asm volatile("ldmatrix.sync.aligned.m8n8.x4.shared.b16 {%0,%1,%2,%3}, [%4];"
                 : "=r"(r[0]), "=r"(r[1]), "=r"(r[2]), "=r"(r[3]) : "r"(addr));
}
__device__ __forceinline__ void mma16816(float* c, const uint32_t* a,
                                         uint32_t b0, uint32_t b1) {
    asm volatile(
        "mma.sync.aligned.m16n8k16.row.col.f32.bf16.bf16.f32 "
        "{%0,%1,%2,%3}, {%4,%5,%6,%7}, {%8,%9}, {%0,%1,%2,%3};"
        : "+f"(c[0]), "+f"(c[1]), "+f"(c[2]), "+f"(c[3])
        : "r"(a[0]), "r"(a[1]), "r"(a[2]), "r"(a[3]), "r"(b0), "r"(b1));
}

// ---------------------------------------------------------------------------
// conversion kernels
// ---------------------------------------------------------------------------
__global__ __launch_bounds__(256)
void cvt_x_kernel(const float* __restrict__ x, int n4, size_t dst)
{
    int i = blockIdx.x * 256 + threadIdx.x;
    if (i >= n4) return;
    float4 v = reinterpret_cast<const float4*>(x)[i];
    float vv[4] = {v.x, v.y, v.z, v.w};
    uint16_t hs[4], ls[4];
#pragma unroll
    for (int j = 0; j < 4; j++) {
        __nv_bfloat16 h = __float2bfloat16(vv[j]);
        __nv_bfloat16 l = __float2bfloat16(vv[j] - __bfloat162float(h));
        hs[j] = __bfloat16_as_ushort(h);
        ls[j] = __bfloat16_as_ushort(l);
    }
    size_t o = dst + (size_t)i * 4;
    *reinterpret_cast<uint2*>(g_xhi + o) =
        make_uint2((uint32_t)hs[0] | ((uint32_t)hs[1] << 16),
                   (uint32_t)hs[2] | ((uint32_t)hs[3] << 16));
    *reinterpret_cast<uint2*>(g_xlo + o) =
        make_uint2((uint32_t)ls[0] | ((uint32_t)ls[1] << 16),
                   (uint32_t)ls[2] | ((uint32_t)ls[3] << 16));
}

// build W^T with tripled K: [n][0:2304)=hi, [2304:4608)=lo, [4608:6912)=hi
__global__ __launch_bounds__(256)
void cvt_w_kernel(const float* __restrict__ wsh)
{
    int i = blockIdx.x * 256 + threadIdx.x;
    if (i >= 512 * 2304) return;
    int n = i / 2304, k = i - n * 2304;
    float v = wsh[(size_t)k * 512 + n];
    __nv_bfloat16 h = __float2bfloat16(v);
    __nv_bfloat16 l = __float2bfloat16(v - __bfloat162float(h));
    size_t base = (size_t)n * K3TOT;
    g_wT3[base + k]        = h;
    g_wT3[base + 2304 + k] = l;
    g_wT3[base + 4608 + k] = h;
}

// ---------------------------------------------------------------------------
// conv3x3 + bias + relu  (implicit GEMM, bf16 HMMA, tripled K)
// grid (M/128, 4), block 256 (8 warps: 4(m) x 2(n)), warp tile 32x64
// ---------------------------------------------------------------------------
__global__ __launch_bounds__(256, 2)
void conv_gemm_kernel(int H, int HH, int levelBase, const float* __restrict__ bsh)
{
    __shared__ __align__(16) char smem[4 * TILE_B];   // A0 B0 A1 B1
    const uint32_t su = smem_u32(smem);
    const uint32_t sA[2] = {su, su + 2 * TILE_B};
    const uint32_t sB[2] = {su + TILE_B, su + 3 * TILE_B};

    const int tid  = threadIdx.x;
    const int wid  = tid >> 5;
    const int lane = tid & 31;
    const int m0   = blockIdx.x * 128;
    const int n0   = blockIdx.y * 128;

    // ---- loader geometry: 512 16B-vectors per operand; 2 per thread
    const int lr  = tid >> 2;       // 0..63 (row base; +64 for second)
    const int seg = tid & 3;        // 16B segment within 32-wide k chunk
    int pb[2], ph[2], pw[2];
#pragma unroll
    for (int i = 0; i < 2; i++) {
        int p = m0 + lr + i * 64;
        pb[i] = p / HH; int rem = p - pb[i] * HH;
        ph[i] = rem / H; pw[i] = rem - ph[i] * H;
    }
    const size_t xbase = (size_t)levelBase * 256;

    // issue one stage's cp.async into buffer `buf`
    auto issue = [&](int s, int buf) {
        int k3 = s * 32;
        int sp = (k3 >= 4608) ? 2 : (k3 >= 2304 ? 1 : 0);
        int krem = k3 - sp * 2304;
        int tap = krem >> 8;
        int ci0 = (krem & 255) + seg * 8;
        int dr = tap / 3 - 1, dc = tap - (tap / 3) * 3 - 1;
        const __nv_bfloat16* xb = (sp == 2) ? g_xlo : g_xhi;
#pragma unroll
        for (int i = 0; i < 2; i++) {
            int row = lr + i * 64;
            int hh = ph[i] + dr, ww = pw[i] + dc;
            bool ok = ((unsigned)hh < (unsigned)H) && ((unsigned)ww < (unsigned)H);
            const void* src = ok
                ? (const void*)(xb + xbase + (((size_t)(pb[i] * H + hh)) * H + ww) * 256 + ci0)
                : (const void*)g_xhi;
            cp_async16(sA[buf] + row * 80 + seg * 16, src, ok ? 16 : 0);
        }
#pragma unroll
        for (int i = 0; i < 2; i++) {
            int row = lr + i * 64;
            const void* src = g_wT3 + (size_t)(n0 + row) * K3TOT + k3 + seg * 8;
            cp_async16(sB[buf] + row * 80 + seg * 16, src, 16);
        }
        cp_commit();
    };

    const int wm = wid >> 1;     // 0..3  -> m group of 32
    const int wn = wid & 1;      // 0..1  -> n group of 64

    float acc[2][8][4];
#pragma unroll
    for (int mi = 0; mi < 2; mi++)
#pragma unroll
        for (int j = 0; j < 8; j++)
#pragma unroll
            for (int e = 0; e < 4; e++) acc[mi][j][e] = 0.f;

    // ldmatrix per-lane address offsets
    const int a_row = (lane & 15);
    const int a_k   = ((lane >> 4) << 3);
    const int b_row = ((lane >> 4) << 3) + (lane & 7);
    const int b_k   = ((lane >> 3) & 1) << 3;

    issue(0, 0);
    for (int s = 0; s < NSTAGE; s++) {
        const int buf = s & 1;
        if (s + 1 < NSTAGE) issue(s + 1, buf ^ 1);
        else                cp_commit();     // keep group count pattern
        cp_wait1();
        __syncthreads();

#pragma unroll
        for (int kk = 0; kk < 32; kk += 16) {
            uint32_t af[2][4];
#pragma unroll
            for (int mi = 0; mi < 2; mi++)
                ldm_x4(af[mi], sA[buf] + (wm * 32 + mi * 16 + a_row) * 80
                                       + (kk + a_k) * 2);
            uint32_t bf[4][4];
#pragma unroll
            for (int q = 0; q < 4; q++)
                ldm_x4(bf[q], sB[buf] + (wn * 64 + q * 16 + b_row) * 80
                                      + (kk + b_k) * 2);
#pragma unroll
            for (int mi = 0; mi < 2; mi++)
#pragma unroll
                for (int j = 0; j < 8; j++)
                    mma16816(acc[mi][j], af[mi],
                             bf[j >> 1][(j & 1) * 2], bf[j >> 1][(j & 1) * 2 + 1]);
        }
        __syncthreads();
    }
    cp_wait0();

    // ---- epilogue: bias + relu -> fp16, stage through smem, coalesced store
    __half* ep = reinterpret_cast<__half*>(smem);   // [128][128]
    const int qr = lane >> 2;         // 0..7
    const int qc = (lane & 3) * 2;    // 0,2,4,6
#pragma unroll
    for (int mi = 0; mi < 2; mi++) {
#pragma unroll
        for (int j = 0; j < 8; j++) {
            int col = wn * 64 + j * 8 + qc;
            float b0 = __ldg(bsh + n0 + col);
            float b1 = __ldg(bsh + n0 + col + 1);
            int r0 = wm * 32 + mi * 16 + qr;
            float v0 = fmaxf(acc[mi][j][0] + b0, 0.f);
            float v1 = fmaxf(acc[mi][j][1] + b1, 0.f);
            float v2 = fmaxf(acc[mi][j][2] + b0, 0.f);
            float v3 = fmaxf(acc[mi][j][3] + b1, 0.f);
            *reinterpret_cast<__half2*>(ep + r0 * 128 + col)       = __floats2half2_rn(v0, v1);
            *reinterpret_cast<__half2*>(ep + (r0 + 8) * 128 + col) = __floats2half2_rn(v2, v3);
        }
    }
    __syncthreads();
#pragma unroll
    for (int t = 0; t < 8; t++) {
        int idx = t * 256 + tid;          // 2048 16B vectors
        int row = idx >> 4, sg = idx & 15;
        uint4 v = *reinterpret_cast<const uint4*>(ep + row * 128 + sg * 8);
        *reinterpret_cast<uint4*>(g_s16 + (size_t)(levelBase + m0 + row) * 512
                                  + n0 + sg * 8) = v;
    }
}

// ---------------------------------------------------------------------------
// heads: 1x1 convs + softmax + scatter (reads fp16 s)
// ---------------------------------------------------------------------------
__global__ __launch_bounds__(256)
void heads_kernel(const float* __restrict__ wcls, const float* __restrict__ bcls,
                  const float* __restrict__ wbox, const float* __restrict__ bbox,
                  float* __restrict__ out_logit, float* __restrict__ out_prob,
                  float* __restrict__ out_box,
                  int HH, int levelOff, int levelBase)
{
    __shared__ float wsm[512 * 18];
    __shared__ float bsm[18];

    const int tid = threadIdx.x;
    for (int i = tid; i < 512 * 6; i += 256) {
        int c = i / 6, o = i - c * 6;
        wsm[c * 18 + o] = wcls[i];
    }
    for (int i = tid; i < 512 * 12; i += 256) {
        int c = i / 12, o = i - c * 12;
        wsm[c * 18 + 6 + o] = wbox[i];
    }
    if (tid < 6)       bsm[tid] = bcls[tid];
    else if (tid < 18) bsm[tid] = bbox[tid - 6];
    __syncthreads();

    const int warp = blockIdx.x * 8 + (tid >> 5);
    const int lane = tid & 31;
    const int p0   = warp * 4;

    float acc[4][18];
#pragma unroll
    for (int px = 0; px < 4; px++)
#pragma unroll
        for (int o = 0; o < 18; o++) acc[px][o] = 0.f;

    const __half* sp = g_s16 + (size_t)(levelBase + p0) * 512 + 2 * lane;
#pragma unroll
    for (int it = 0; it < 8; it++) {
        const int c = 2 * lane + it * 64;
        float2 sv[4];
#pragma unroll
        for (int px = 0; px < 4; px++)
            sv[px] = __half22float2(
                *reinterpret_cast<const __half2*>(sp + (size_t)px * 512 + it * 64));
        const float* w0 = &wsm[c * 18];
        const float* w1 = &wsm[(c + 1) * 18];
#pragma unroll
        for (int o = 0; o < 18; o++) {
            float wv0 = w0[o], wv1 = w1[o];
#pragma unroll
            for (int px = 0; px < 4; px++)
                acc[px][o] += sv[px].x * wv0 + sv[px].y * wv1;
        }
    }

#pragma unroll
    for (int off = 16; off; off >>= 1)
#pragma unroll
        for (int px = 0; px < 4; px++)
#pragma unroll
            for (int o = 0; o < 18; o++)
                acc[px][o] += __shfl_xor_sync(0xffffffffu, acc[px][o], off);

    if (lane < 18) {
        const int o = lane;
        const float bo = bsm[o];
#pragma unroll
        for (int px = 0; px < 4; px++) {
            int m = p0 + px;
            int b = m / HH; int rem = m - b * HH;
            if (o < 6) {
                int pair = o & ~1;
                int a    = o >> 1;
                int cls  = o & 1;
                float l0 = acc[px][pair]     + bsm[pair];
                float l1 = acc[px][pair + 1] + bsm[pair + 1];
                float lv = (cls == 0) ? l0 : l1;
                float mx = fmaxf(l0, l1);
                float e0 = expf(l0 - mx), e1 = expf(l1 - mx);
                float pr = ((cls == 0) ? e0 : e1) / (e0 + e1);
                int pos = levelOff + rem * 3 + a;
                int idx = (b * TOT_POS + pos) * 2 + cls;
                out_logit[idx] = lv;
                out_prob[idx]  = pr;
            } else {
                int oo = o - 6;
                int a = oo >> 2, coord = oo & 3;
                int pos = levelOff + rem * 3 + a;
                out_box[(b * TOT_POS + pos) * 4 + coord] = acc[px][o] + bo;
            }
        }
    }
}

// ---------------------------------------------------------------------------
extern "C" void kernel_launch(void* const* d_in, const int* in_sizes, int n_in,
                              void* d_out, int out_size)
{
    const float* p[5];
    for (int i = 0; i < 5; i++) p[i] = (const float*)d_in[i];
    const float* w_share = (const float*)d_in[5];
    const float* b_share = (const float*)d_in[6];
    const float* w_cls   = (const float*)d_in[7];
    const float* b_cls   = (const float*)d_in[8];
    const float* w_box   = (const float*)d_in[9];
    const float* b_box   = (const float*)d_in[10];
    float* out = (float*)d_out;

    float* out_logit = out;
    float* out_prob  = out + (size_t)2 * TOT_POS * 2;
    float* out_box   = out + (size_t)4 * TOT_POS * 2;

    const int Hs[5]        = {256, 128, 64, 32, 16};
    const int levelBase[5] = {0, 131072, 163840, 172032, 174080};
    const int offs[5]      = {0, 196608, 245760, 258048, 261120};

    for (int lvl = 0; lvl < 5; lvl++) {
        int M  = 2 * Hs[lvl] * Hs[lvl];
        int n4 = M * 64;
        cvt_x_kernel<<<(n4 + 255) / 256, 256>>>(p[lvl], n4,
                                                (size_t)levelBase[lvl] * 256);
    }
    cvt_w_kernel<<<(512 * 2304 + 255) / 256, 256>>>(w_share);

    for (int lvl = 0; lvl < 5; lvl++) {
        int H  = Hs[lvl];
        int HH = H * H;
        int M  = 2 * HH;
        dim3 grid(M / 128, 4);
        conv_gemm_kernel<<<grid, 256>>>(H, HH, levelBase[lvl], b_share);
        heads_kernel<<<M / 32, 256>>>(w_cls, b_cls, w_box, b_box,
                                      out_logit, out_prob, out_box,
                                      HH, offs[lvl], levelBase[lvl]);
    }
}

// round 4
// speedup vs baseline: 2.2227x; 1.0232x over previous
#include <cuda_runtime.h>
#include <cuda_bf16.h>
#include <cuda_fp16.h>
#include <cstdint>
#include <cstddef>

// ============================================================================
// RPNHead: 3-split bf16 mma.sync implicit GEMM (tripled K), CTA 128x256,
// all pyramid levels fused into one launch; fp16 s scratch; fused heads.
// ============================================================================

#define TOTM     174592
#define TOT_POS  261888
#define K3TOT    6912            // 3 * 9 * 256
#define NSTAGE   216             // K3TOT / 32

// padded smem rows: 32 bf16 + 8 pad = 80 bytes
#define A_TILE_B (128 * 80)      // 10240
#define B_TILE_B (256 * 80)      // 20480
#define STAGE_B  (A_TILE_B + B_TILE_B)   // 30720
#define SMEM_DYN (3 * STAGE_B)   // 92160

__device__ __align__(16) __nv_bfloat16 g_xhi[(size_t)TOTM * 256];
__device__ __align__(16) __nv_bfloat16 g_xlo[(size_t)TOTM * 256];
__device__ __align__(16) __nv_bfloat16 g_wT3[(size_t)512 * K3TOT];
__device__ __align__(16) __half        g_s16[(size_t)TOTM * 512];

// ---------------------------------------------------------------------------
__device__ __forceinline__ uint32_t smem_u32(const void* p) {
    uint32_t a;
    asm("{ .reg .u64 t; cvta.to.shared.u64 t, %1; cvt.u32.u64 %0, t; }"
        : "=r"(a) : "l"(p));
    return a;
}
__device__ __forceinline__ void cp_async16(uint32_t dst, const void* src, int sz) {
    asm volatile("cp.async.ca.shared.global [%0], [%1], 16, %2;"
                 :: "r"(dst), "l"(src), "r"(sz) : "memory");
}
__device__ __forceinline__ void cp_commit() {
    asm volatile("cp.async.commit_group;" ::: "memory");
}
__device__ __forceinline__ void cp_wait2() {
    asm volatile("cp.async.wait_group 2;" ::: "memory");
}
__device__ __forceinline__ void ldm_x4(uint32_t* r, uint32_t addr) {
    asm volatile("ldmatrix.sync.aligned.m8n8.x4.shared.b16 {%0,%1,%2,%3}, [%4];"
                 : "=r"(r[0]), "=r"(r[1]), "=r"(r[2]), "=r"(r[3]) : "r"(addr));
}
__device__ __forceinline__ void mma16816(float* c, const uint32_t* a,
                                         uint32_t b0, uint32_t b1) {
    asm volatile(
        "mma.sync.aligned.m16n8k16.row.col.f32.bf16.bf16.f32 "
        "{%0,%1,%2,%3}, {%4,%5,%6,%7}, {%8,%9}, {%0,%1,%2,%3};"
        : "+f"(c[0]), "+f"(c[1]), "+f"(c[2]), "+f"(c[3])
        : "r"(a[0]), "r"(a[1]), "r"(a[2]), "r"(a[3]), "r"(b0), "r"(b1));
}

// level tables
__device__ __forceinline__ int lvl_of_blk(int mb) {
    return (mb >= 1360) ? 4 : (mb >= 1344) ? 3 : (mb >= 1280) ? 2
         : (mb >= 1024) ? 1 : 0;
}
__device__ __forceinline__ int lvl_of_pix(int gp) {
    return (gp >= 174080) ? 4 : (gp >= 172032) ? 3 : (gp >= 163840) ? 2
         : (gp >= 131072) ? 1 : 0;
}
__constant__ int c_H[5]      = {256, 128, 64, 32, 16};
__constant__ int c_pixB[5]   = {0, 131072, 163840, 172032, 174080};
__constant__ int c_blkB[5]   = {0, 1024, 1280, 1344, 1360};
__constant__ int c_posOff[5] = {0, 196608, 245760, 258048, 261120};

// ---------------------------------------------------------------------------
// conversion kernels (single launch each)
// ---------------------------------------------------------------------------
__global__ __launch_bounds__(256)
void cvt_x_kernel(const float* __restrict__ x0, const float* __restrict__ x1,
                  const float* __restrict__ x2, const float* __restrict__ x3,
                  const float* __restrict__ x4)
{
    int i = blockIdx.x * 256 + threadIdx.x;       // vec index (4 floats)
    if (i >= TOTM * 64) return;
    int l = (i >= 174080 * 64) ? 4 : (i >= 172032 * 64) ? 3
          : (i >= 163840 * 64) ? 2 : (i >= 131072 * 64) ? 1 : 0;
    const float* xs[5] = {x0, x1, x2, x3, x4};
    int li = i - c_pixB[l] * 64;
    float4 v = reinterpret_cast<const float4*>(xs[l])[li];
    float vv[4] = {v.x, v.y, v.z, v.w};
    uint16_t hs[4], ls[4];
#pragma unroll
    for (int j = 0; j < 4; j++) {
        __nv_bfloat16 h = __float2bfloat16(vv[j]);
        __nv_bfloat16 l2 = __float2bfloat16(vv[j] - __bfloat162float(h));
        hs[j] = __bfloat16_as_ushort(h);
        ls[j] = __bfloat16_as_ushort(l2);
    }
    size_t o = (size_t)i * 4;
    *reinterpret_cast<uint2*>(g_xhi + o) =
        make_uint2((uint32_t)hs[0] | ((uint32_t)hs[1] << 16),
                   (uint32_t)hs[2] | ((uint32_t)hs[3] << 16));
    *reinterpret_cast<uint2*>(g_xlo + o) =
        make_uint2((uint32_t)ls[0] | ((uint32_t)ls[1] << 16),
                   (uint32_t)ls[2] | ((uint32_t)ls[3] << 16));
}

__global__ __launch_bounds__(256)
void cvt_w_kernel(const float* __restrict__ wsh)
{
    int i = blockIdx.x * 256 + threadIdx.x;
    if (i >= 512 * 2304) return;
    int n = i / 2304, k = i - n * 2304;
    float v = wsh[(size_t)k * 512 + n];
    __nv_bfloat16 h = __float2bfloat16(v);
    __nv_bfloat16 l = __float2bfloat16(v - __bfloat162float(h));
    size_t base = (size_t)n * K3TOT;
    g_wT3[base + k]        = h;
    g_wT3[base + 2304 + k] = l;
    g_wT3[base + 4608 + k] = h;
}

// ---------------------------------------------------------------------------
// conv3x3 + bias + relu  (implicit GEMM, bf16 HMMA, tripled K), ALL levels.
// grid (1364, 2), block 512 (16 warps: 4m x 4n), warp tile 32x64.
// ---------------------------------------------------------------------------
__global__ __launch_bounds__(512, 1)
void conv_gemm_kernel(const float* __restrict__ bsh)
{
    extern __shared__ __align__(16) char smem[];
    const uint32_t su = smem_u32(smem);

    const int tid  = threadIdx.x;
    const int wid  = tid >> 5;
    const int lane = tid & 31;
    const int mb   = blockIdx.x;
    const int n0   = blockIdx.y * 256;

    const int l    = lvl_of_blk(mb);
    const int H    = c_H[l];
    const int HH   = H * H;
    const int pixB = c_pixB[l] + (mb - c_blkB[l]) * 128;   // global pixel base

    // ---- loader geometry ----
    // A: 512 vecs (128 rows x 4 segs) -> 1/thread
    const int a_row = tid >> 2;
    const int a_seg = tid & 3;
    int pb, phh, pww;
    {
        int p = (pixB - c_pixB[l]) + a_row;    // level-local pixel
        pb = p / HH; int rem = p - pb * HH;
        phh = rem / H; pww = rem - phh * H;
    }
    // B: 1024 vecs (256 rows x 4 segs) -> 2/thread (rows r, r+128)
    const int b_rowv = tid >> 2;          // 0..127
    const int b_segv = tid & 3;
    const size_t xlevel = (size_t)c_pixB[l] * 256;

    auto issue = [&](int s, int buf) {
        const uint32_t sb = su + buf * STAGE_B;
        int k3 = s * 32;
        int sp = (k3 >= 4608) ? 2 : (k3 >= 2304 ? 1 : 0);
        int krem = k3 - sp * 2304;
        int tap = krem >> 8;
        int kin = krem & 255;
        int dr = tap / 3 - 1, dc = tap - (tap / 3) * 3 - 1;
        const __nv_bfloat16* xb = (sp == 2) ? g_xlo : g_xhi;
        // A
        {
            int hh = phh + dr, ww = pww + dc;
            bool ok = ((unsigned)hh < (unsigned)H) && ((unsigned)ww < (unsigned)H);
            const void* src = ok
                ? (const void*)(xb + xlevel
                    + (((size_t)(pb * H + hh)) * H + ww) * 256 + kin + a_seg * 8)
                : (const void*)g_xhi;
            cp_async16(sb + a_row * 80 + a_seg * 16, src, ok ? 16 : 0);
        }
        // B
#pragma unroll
        for (int i = 0; i < 2; i++) {
            int row = b_rowv + i * 128;
            const void* src = g_wT3 + (size_t)(n0 + row) * K3TOT + k3 + b_segv * 8;
            cp_async16(sb + A_TILE_B + row * 80 + b_segv * 16, src, 16);
        }
        cp_commit();
    };

    const int wm = wid >> 2;     // 0..3 -> 32-row group
    const int wn = wid & 3;      // 0..3 -> 64-col group

    float acc[2][8][4];
#pragma unroll
    for (int mi = 0; mi < 2; mi++)
#pragma unroll
        for (int j = 0; j < 8; j++)
#pragma unroll
            for (int e = 0; e < 4; e++) acc[mi][j][e] = 0.f;

    const int la_row = (lane & 15);
    const int la_k   = ((lane >> 4) << 3);
    const int lb_row = ((lane >> 4) << 3) + (lane & 7);
    const int lb_k   = ((lane >> 3) & 1) << 3;

    issue(0, 0);
    issue(1, 1);
#pragma unroll 1
    for (int s = 0; s < NSTAGE; s++) {
        const int buf = s % 3;
        if (s + 2 < NSTAGE) issue(s + 2, (s + 2) % 3);
        else                cp_commit();
        cp_wait2();
        __syncthreads();

        const uint32_t sA = su + buf * STAGE_B;
        const uint32_t sB = sA + A_TILE_B;
#pragma unroll
        for (int kk = 0; kk < 32; kk += 16) {
            uint32_t af[2][4];
#pragma unroll
            for (int mi = 0; mi < 2; mi++)
                ldm_x4(af[mi], sA + (wm * 32 + mi * 16 + la_row) * 80
                                  + (kk + la_k) * 2);
            uint32_t bf[4][4];
#pragma unroll
            for (int q = 0; q < 4; q++)
                ldm_x4(bf[q], sB + (wn * 64 + q * 16 + lb_row) * 80
                                 + (kk + lb_k) * 2);
#pragma unroll
            for (int mi = 0; mi < 2; mi++)
#pragma unroll
                for (int j = 0; j < 8; j++)
                    mma16816(acc[mi][j], af[mi],
                             bf[j >> 1][(j & 1) * 2], bf[j >> 1][(j & 1) * 2 + 1]);
        }
        __syncthreads();
    }

    // ---- epilogue: bias + relu -> fp16, stage through smem, coalesced store
    __half* ep = reinterpret_cast<__half*>(smem);   // [128][256] = 64KB
    const int qr = lane >> 2;
    const int qc = (lane & 3) * 2;
#pragma unroll
    for (int mi = 0; mi < 2; mi++) {
#pragma unroll
        for (int j = 0; j < 8; j++) {
            int col = wn * 64 + j * 8 + qc;
            float b0 = __ldg(bsh + n0 + col);
            float b1 = __ldg(bsh + n0 + col + 1);
            int r0 = wm * 32 + mi * 16 + qr;
            float v0 = fmaxf(acc[mi][j][0] + b0, 0.f);
            float v1 = fmaxf(acc[mi][j][1] + b1, 0.f);
            float v2 = fmaxf(acc[mi][j][2] + b0, 0.f);
            float v3 = fmaxf(acc[mi][j][3] + b1, 0.f);
            *reinterpret_cast<__half2*>(ep + r0 * 256 + col)       = __floats2half2_rn(v0, v1);
            *reinterpret_cast<__half2*>(ep + (r0 + 8) * 256 + col) = __floats2half2_rn(v2, v3);
        }
    }
    __syncthreads();
#pragma unroll
    for (int t = 0; t < 8; t++) {
        int idx = t * 512 + tid;          // 4096 16B vectors
        int row = idx >> 5, sg = idx & 31;
        uint4 v = *reinterpret_cast<const uint4*>(ep + row * 256 + sg * 8);
        *reinterpret_cast<uint4*>(g_s16 + (size_t)(pixB + row) * 512
                                  + n0 + sg * 8) = v;
    }
}

// ---------------------------------------------------------------------------
// heads: 1x1 convs + softmax + scatter (single launch over all pixels)
// ---------------------------------------------------------------------------
__global__ __launch_bounds__(256)
void heads_kernel(const float* __restrict__ wcls, const float* __restrict__ bcls,
                  const float* __restrict__ wbox, const float* __restrict__ bbox,
                  float* __restrict__ out_logit, float* __restrict__ out_prob,
                  float* __restrict__ out_box)
{
    __shared__ float wsm[512 * 18];
    __shared__ float bsm[18];

    const int tid = threadIdx.x;
    for (int i = tid; i < 512 * 6; i += 256) {
        int c = i / 6, o = i - c * 6;
        wsm[c * 18 + o] = wcls[i];
    }
    for (int i = tid; i < 512 * 12; i += 256) {
        int c = i / 12, o = i - c * 12;
        wsm[c * 18 + 6 + o] = wbox[i];
    }
    if (tid < 6)       bsm[tid] = bcls[tid];
    else if (tid < 18) bsm[tid] = bbox[tid - 6];
    __syncthreads();

    const int warp = blockIdx.x * 8 + (tid >> 5);
    const int lane = tid & 31;
    const int p0   = warp * 4;                     // global pixel

    float acc[4][18];
#pragma unroll
    for (int px = 0; px < 4; px++)
#pragma unroll
        for (int o = 0; o < 18; o++) acc[px][o] = 0.f;

    const __half* sp = g_s16 + (size_t)p0 * 512 + 2 * lane;
#pragma unroll
    for (int it = 0; it < 8; it++) {
        const int c = 2 * lane + it * 64;
        float2 sv[4];
#pragma unroll
        for (int px = 0; px < 4; px++)
            sv[px] = __half22float2(
                *reinterpret_cast<const __half2*>(sp + (size_t)px * 512 + it * 64));
        const float* w0 = &wsm[c * 18];
        const float* w1 = &wsm[(c + 1) * 18];
#pragma unroll
        for (int o = 0; o < 18; o++) {
            float wv0 = w0[o], wv1 = w1[o];
#pragma unroll
            for (int px = 0; px < 4; px++)
                acc[px][o] += sv[px].x * wv0 + sv[px].y * wv1;
        }
    }

#pragma unroll
    for (int off = 16; off; off >>= 1)
#pragma unroll
        for (int px = 0; px < 4; px++)
#pragma unroll
            for (int o = 0; o < 18; o++)
                acc[px][o] += __shfl_xor_sync(0xffffffffu, acc[px][o], off);

    if (lane < 18) {
        const int o = lane;
        const float bo = bsm[o];
#pragma unroll
        for (int px = 0; px < 4; px++) {
            int gp = p0 + px;
            int l  = lvl_of_pix(gp);
            int HH = c_H[l] * c_H[l];
            int pl = gp - c_pixB[l];
            int b  = pl / HH; int rem = pl - b * HH;
            if (o < 6) {
                int pair = o & ~1;
                int a    = o >> 1;
                int cls  = o & 1;
                float l0 = acc[px][pair]     + bsm[pair];
                float l1 = acc[px][pair + 1] + bsm[pair + 1];
                float lv = (cls == 0) ? l0 : l1;
                float mx = fmaxf(l0, l1);
                float e0 = expf(l0 - mx), e1 = expf(l1 - mx);
                float pr = ((cls == 0) ? e0 : e1) / (e0 + e1);
                int pos = c_posOff[l] + rem * 3 + a;
                int idx = (b * TOT_POS + pos) * 2 + cls;
                out_logit[idx] = lv;
                out_prob[idx]  = pr;
            } else {
                int oo = o - 6;
                int a = oo >> 2, coord = oo & 3;
                int pos = c_posOff[l] + rem * 3 + a;
                out_box[(b * TOT_POS + pos) * 4 + coord] = acc[px][o] + bo;
            }
        }
    }
}

// ---------------------------------------------------------------------------
extern "C" void kernel_launch(void* const* d_in, const int* in_sizes, int n_in,
                              void* d_out, int out_size)
{
    const float* p0 = (const float*)d_in[0];
    const float* p1 = (const float*)d_in[1];
    const float* p2 = (const float*)d_in[2];
    const float* p3 = (const float*)d_in[3];
    const float* p4 = (const float*)d_in[4];
    const float* w_share = (const float*)d_in[5];
    const float* b_share = (const float*)d_in[6];
    const float* w_cls   = (const float*)d_in[7];
    const float* b_cls   = (const float*)d_in[8];
    const float* w_box   = (const float*)d_in[9];
    const float* b_box   = (const float*)d_in[10];
    float* out = (float*)d_out;

    float* out_logit = out;
    float* out_prob  = out + (size_t)2 * TOT_POS * 2;
    float* out_box   = out + (size_t)4 * TOT_POS * 2;

    cudaFuncSetAttribute(conv_gemm_kernel,
                         cudaFuncAttributeMaxDynamicSharedMemorySize, SMEM_DYN);

    cvt_x_kernel<<<(TOTM * 64 + 255) / 256, 256>>>(p0, p1, p2, p3, p4);
    cvt_w_kernel<<<(512 * 2304 + 255) / 256, 256>>>(w_share);

    dim3 grid(1364, 2);
    conv_gemm_kernel<<<grid, 512, SMEM_DYN>>>(b_share);

    heads_kernel<<<TOTM / 32, 256>>>(w_cls, b_cls, w_box, b_box,
                                     out_logit, out_prob, out_box);
}

// round 5
// speedup vs baseline: 6.4023x; 2.8804x over previous
#include <cuda_runtime.h>
#include <cuda_fp16.h>
#include <cstdint>
#include <cstddef>

// ============================================================================
// RPNHead: single-pass fp16 mma.sync implicit GEMM (K=2304), CTA 128x256,
// all levels fused; fp16 s scratch; HMMA-based fused heads + softmax.
// ============================================================================

#define TOTM     174592
#define TOT_POS  261888
#define KTOT     2304            // 9 * 256
#define NSTAGE   72              // KTOT / 32

// conv smem: padded rows 32 fp16 + 8 pad = 80 bytes
#define A_TILE_B (128 * 80)
#define B_TILE_B (256 * 80)
#define STAGE_B  (A_TILE_B + B_TILE_B)   // 30720
#define SMEM_DYN (3 * STAGE_B)           // 92160

// heads smem layout (bytes)
#define HW_PITCH 1040            // 520 halfs per w row
#define HS_PITCH 144             // 64 halfs + pad
#define H_S0     25088
#define H_S1     43520
#define H_BIAS   61952
#define H_SMEM   62080

__device__ __align__(16) __half g_x16[(size_t)TOTM * 256];
__device__ __align__(16) __half g_wT [(size_t)512 * KTOT];
__device__ __align__(16) __half g_wh [24 * 512];
__device__ __align__(16) __half g_s16[(size_t)TOTM * 512];

// ---------------------------------------------------------------------------
__device__ __forceinline__ uint32_t smem_u32(const void* p) {
    uint32_t a;
    asm("{ .reg .u64 t; cvta.to.shared.u64 t, %1; cvt.u32.u64 %0, t; }"
        : "=r"(a) : "l"(p));
    return a;
}
__device__ __forceinline__ void cp_async16(uint32_t dst, const void* src, int sz) {
    asm volatile("cp.async.ca.shared.global [%0], [%1], 16, %2;"
                 :: "r"(dst), "l"(src), "r"(sz) : "memory");
}
__device__ __forceinline__ void cp_commit() {
    asm volatile("cp.async.commit_group;" ::: "memory");
}
__device__ __forceinline__ void cp_wait1() {
    asm volatile("cp.async.wait_group 1;" ::: "memory");
}
__device__ __forceinline__ void cp_wait2() {
    asm volatile("cp.async.wait_group 2;" ::: "memory");
}
__device__ __forceinline__ void ldm_x4(uint32_t* r, uint32_t addr) {
    asm volatile("ldmatrix.sync.aligned.m8n8.x4.shared.b16 {%0,%1,%2,%3}, [%4];"
                 : "=r"(r[0]), "=r"(r[1]), "=r"(r[2]), "=r"(r[3]) : "r"(addr));
}
__device__ __forceinline__ void ldm_x2(uint32_t* r, uint32_t addr) {
    asm volatile("ldmatrix.sync.aligned.m8n8.x2.shared.b16 {%0,%1}, [%2];"
                 : "=r"(r[0]), "=r"(r[1]) : "r"(addr));
}
__device__ __forceinline__ void mma16816(float* c, const uint32_t* a,
                                         uint32_t b0, uint32_t b1) {
    asm volatile(
        "mma.sync.aligned.m16n8k16.row.col.f32.f16.f16.f32 "
        "{%0,%1,%2,%3}, {%4,%5,%6,%7}, {%8,%9}, {%0,%1,%2,%3};"
        : "+f"(c[0]), "+f"(c[1]), "+f"(c[2]), "+f"(c[3])
        : "r"(a[0]), "r"(a[1]), "r"(a[2]), "r"(a[3]), "r"(b0), "r"(b1));
}

__device__ __forceinline__ int lvl_of_blk(int mb) {
    return (mb >= 1360) ? 4 : (mb >= 1344) ? 3 : (mb >= 1280) ? 2
         : (mb >= 1024) ? 1 : 0;
}
__constant__ int c_H[5]      = {256, 128, 64, 32, 16};
__constant__ int c_pixB[5]   = {0, 131072, 163840, 172032, 174080};
__constant__ int c_blkB[5]   = {0, 1024, 1280, 1344, 1360};
__constant__ int c_posOff[5] = {0, 196608, 245760, 258048, 261120};

// ---------------------------------------------------------------------------
// conversion kernels
// ---------------------------------------------------------------------------
__global__ __launch_bounds__(256)
void cvt_x_kernel(const float* __restrict__ x0, const float* __restrict__ x1,
                  const float* __restrict__ x2, const float* __restrict__ x3,
                  const float* __restrict__ x4)
{
    int i = blockIdx.x * 256 + threadIdx.x;       // vec index (4 floats)
    if (i >= TOTM * 64) return;
    int l = (i >= 174080 * 64) ? 4 : (i >= 172032 * 64) ? 3
          : (i >= 163840 * 64) ? 2 : (i >= 131072 * 64) ? 1 : 0;
    const float* xs[5] = {x0, x1, x2, x3, x4};
    int li = i - c_pixB[l] * 64;
    float4 v = reinterpret_cast<const float4*>(xs[l])[li];
    __half2 h01 = __floats2half2_rn(v.x, v.y);
    __half2 h23 = __floats2half2_rn(v.z, v.w);
    *reinterpret_cast<uint2*>(g_x16 + (size_t)i * 4) =
        make_uint2(*reinterpret_cast<uint32_t*>(&h01),
                   *reinterpret_cast<uint32_t*>(&h23));
}

__global__ __launch_bounds__(256)
void cvt_w_kernel(const float* __restrict__ wsh)
{
    int i = blockIdx.x * 256 + threadIdx.x;
    if (i >= 512 * KTOT) return;
    int n = i / KTOT, k = i - n * KTOT;
    g_wT[(size_t)n * KTOT + k] = __float2half_rn(wsh[(size_t)k * 512 + n]);
}

__global__ __launch_bounds__(512)
void cvt_wh_kernel(const float* __restrict__ wcls, const float* __restrict__ wbox)
{
    int c = threadIdx.x;   // 0..511
#pragma unroll
    for (int o = 0; o < 24; o++) {
        float v = 0.f;
        if (o < 6)       v = wcls[(size_t)c * 6 + o];
        else if (o < 18) v = wbox[(size_t)c * 12 + (o - 6)];
        g_wh[o * 512 + c] = __float2half_rn(v);
    }
}

// ---------------------------------------------------------------------------
// conv3x3 + bias + relu  (implicit GEMM, fp16 HMMA, single pass), ALL levels.
// grid (1364, 2), block 512 (16 warps: 4m x 4n), warp tile 32x64.
// ---------------------------------------------------------------------------
__global__ __launch_bounds__(512, 1)
void conv_gemm_kernel(const float* __restrict__ bsh)
{
    extern __shared__ __align__(16) char smem[];
    const uint32_t su = smem_u32(smem);

    const int tid  = threadIdx.x;
    const int wid  = tid >> 5;
    const int lane = tid & 31;
    const int mb   = blockIdx.x;
    const int n0   = blockIdx.y * 256;

    const int l    = lvl_of_blk(mb);
    const int H    = c_H[l];
    const int HH   = H * H;
    const int pixB = c_pixB[l] + (mb - c_blkB[l]) * 128;

    // A: 512 vecs (128 rows x 4 segs) -> 1/thread
    const int a_row = tid >> 2;
    const int a_seg = tid & 3;
    int pb, phh, pww;
    {
        int p = (pixB - c_pixB[l]) + a_row;
        pb = p / HH; int rem = p - pb * HH;
        phh = rem / H; pww = rem - phh * H;
    }
    const int b_rowv = tid >> 2;
    const int b_segv = tid & 3;
    const size_t xlevel = (size_t)c_pixB[l] * 256;

    auto issue = [&](int s, int buf) {
        const uint32_t sb = su + buf * STAGE_B;
        int k0 = s * 32;
        int tap = k0 >> 8;
        int kin = k0 & 255;
        int dr = tap / 3 - 1, dc = tap - (tap / 3) * 3 - 1;
        {
            int hh = phh + dr, ww = pww + dc;
            bool ok = ((unsigned)hh < (unsigned)H) && ((unsigned)ww < (unsigned)H);
            const void* src = ok
                ? (const void*)(g_x16 + xlevel
                    + (((size_t)(pb * H + hh)) * H + ww) * 256 + kin + a_seg * 8)
                : (const void*)g_x16;
            cp_async16(sb + a_row * 80 + a_seg * 16, src, ok ? 16 : 0);
        }
#pragma unroll
        for (int i = 0; i < 2; i++) {
            int row = b_rowv + i * 128;
            const void* src = g_wT + (size_t)(n0 + row) * KTOT + k0 + b_segv * 8;
            cp_async16(sb + A_TILE_B + row * 80 + b_segv * 16, src, 16);
        }
        cp_commit();
    };

    const int wm = wid >> 2;
    const int wn = wid & 3;

    float acc[2][8][4];
#pragma unroll
    for (int mi = 0; mi < 2; mi++)
#pragma unroll
        for (int j = 0; j < 8; j++)
#pragma unroll
            for (int e = 0; e < 4; e++) acc[mi][j][e] = 0.f;

    const int la_row = (lane & 15);
    const int la_k   = ((lane >> 4) << 3);
    const int lb_row = ((lane >> 4) << 3) + (lane & 7);
    const int lb_k   = ((lane >> 3) & 1) << 3;

    issue(0, 0);
    issue(1, 1);
#pragma unroll 1
    for (int s = 0; s < NSTAGE; s++) {
        const int buf = s % 3;
        if (s + 2 < NSTAGE) issue(s + 2, (s + 2) % 3);
        else                cp_commit();
        cp_wait2();
        __syncthreads();

        const uint32_t sA = su + buf * STAGE_B;
        const uint32_t sB = sA + A_TILE_B;
#pragma unroll
        for (int kk = 0; kk < 32; kk += 16) {
            uint32_t af[2][4];
#pragma unroll
            for (int mi = 0; mi < 2; mi++)
                ldm_x4(af[mi], sA + (wm * 32 + mi * 16 + la_row) * 80
                                  + (kk + la_k) * 2);
            uint32_t bf[4][4];
#pragma unroll
            for (int q = 0; q < 4; q++)
                ldm_x4(bf[q], sB + (wn * 64 + q * 16 + lb_row) * 80
                                 + (kk + lb_k) * 2);
#pragma unroll
            for (int mi = 0; mi < 2; mi++)
#pragma unroll
                for (int j = 0; j < 8; j++)
                    mma16816(acc[mi][j], af[mi],
                             bf[j >> 1][(j & 1) * 2], bf[j >> 1][(j & 1) * 2 + 1]);
        }
        __syncthreads();
    }

    // epilogue: bias + relu -> fp16, stage through smem, coalesced store
    __half* ep = reinterpret_cast<__half*>(smem);   // [128][256]
    const int qr = lane >> 2;
    const int qc = (lane & 3) * 2;
#pragma unroll
    for (int mi = 0; mi < 2; mi++) {
#pragma unroll
        for (int j = 0; j < 8; j++) {
            int col = wn * 64 + j * 8 + qc;
            float b0 = __ldg(bsh + n0 + col);
            float b1 = __ldg(bsh + n0 + col + 1);
            int r0 = wm * 32 + mi * 16 + qr;
            float v0 = fmaxf(acc[mi][j][0] + b0, 0.f);
            float v1 = fmaxf(acc[mi][j][1] + b1, 0.f);
            float v2 = fmaxf(acc[mi][j][2] + b0, 0.f);
            float v3 = fmaxf(acc[mi][j][3] + b1, 0.f);
            *reinterpret_cast<__half2*>(ep + r0 * 256 + col)       = __floats2half2_rn(v0, v1);
            *reinterpret_cast<__half2*>(ep + (r0 + 8) * 256 + col) = __floats2half2_rn(v2, v3);
        }
    }
    __syncthreads();
#pragma unroll
    for (int t = 0; t < 8; t++) {
        int idx = t * 512 + tid;
        int row = idx >> 5, sg = idx & 31;
        uint4 v = *reinterpret_cast<const uint4*>(ep + row * 256 + sg * 8);
        *reinterpret_cast<uint4*>(g_s16 + (size_t)(pixB + row) * 512
                                  + n0 + sg * 8) = v;
    }
}

// ---------------------------------------------------------------------------
// heads: s[128x512] @ whead^T[24x512] via HMMA, fused softmax + scatter.
// grid 1364, block 128 (4 warps, warp tile 32x24).
// ---------------------------------------------------------------------------
__global__ __launch_bounds__(128)
void heads_kernel(const float* __restrict__ bcls, const float* __restrict__ bbox,
                  float* __restrict__ out_logit, float* __restrict__ out_prob,
                  float* __restrict__ out_box)
{
    extern __shared__ __align__(16) char smem[];
    const uint32_t su = smem_u32(smem);
    float* bsm = reinterpret_cast<float*>(smem + H_BIAS);

    const int tid  = threadIdx.x;
    const int wid  = tid >> 5;
    const int lane = tid & 31;
    const int mb   = blockIdx.x;

    const int l    = lvl_of_blk(mb);
    const int H    = c_H[l];
    const int HH   = H * H;
    const int lpix = (mb - c_blkB[l]) * 128;            // level-local pixel base
    const int gpix = c_pixB[l] + lpix;                  // global pixel base

    // stage head weights [24][512] fp16, pitch 1040B
    for (int i = tid; i < 24 * 64; i += 128) {
        int r = i >> 6, sg = i & 63;
        *reinterpret_cast<uint4*>(smem + r * HW_PITCH + sg * 16) =
            *reinterpret_cast<const uint4*>(g_wh + r * 512 + sg * 8);
    }
    if (tid < 6)       bsm[tid] = bcls[tid];
    else if (tid < 18) bsm[tid] = bbox[tid - 6];

    auto sload = [&](int ck, int buf) {
#pragma unroll
        for (int j = 0; j < 8; j++) {
            int v = tid + j * 128;
            int row = v >> 3, sg = v & 7;
            cp_async16(su + (buf ? H_S1 : H_S0) + row * HS_PITCH + sg * 16,
                       g_s16 + (size_t)(gpix + row) * 512 + ck * 64 + sg * 8, 16);
        }
        cp_commit();
    };

    float acc[2][3][4];
#pragma unroll
    for (int mi = 0; mi < 2; mi++)
#pragma unroll
        for (int nt = 0; nt < 3; nt++)
#pragma unroll
            for (int e = 0; e < 4; e++) acc[mi][nt][e] = 0.f;

    sload(0, 0);
    __syncthreads();     // w + bias visible

#pragma unroll 1
    for (int ck = 0; ck < 8; ck++) {
        const int buf = ck & 1;
        if (ck + 1 < 8) sload(ck + 1, buf ^ 1);
        else            cp_commit();
        cp_wait1();
        __syncthreads();

        const uint32_t sb = su + (buf ? H_S1 : H_S0);
#pragma unroll
        for (int k16 = 0; k16 < 4; k16++) {
            uint32_t af[2][4];
#pragma unroll
            for (int mi = 0; mi < 2; mi++)
                ldm_x4(af[mi], sb + (wid * 32 + mi * 16 + (lane & 15)) * HS_PITCH
                                  + (k16 * 16 + ((lane >> 4) << 3)) * 2);
            int kcol = (ck * 64 + k16 * 16 + (((lane >> 3) & 1) << 3)) * 2;
            uint32_t b01[4], b2[2];
            ldm_x4(b01, su + (((lane >> 4) << 3) + (lane & 7)) * HW_PITCH + kcol);
            ldm_x2(b2,  su + (16 + (lane & 7)) * HW_PITCH + kcol);
#pragma unroll
            for (int mi = 0; mi < 2; mi++) {
                mma16816(acc[mi][0], af[mi], b01[0], b01[1]);
                mma16816(acc[mi][1], af[mi], b01[2], b01[3]);
                mma16816(acc[mi][2], af[mi], b2[0],  b2[1]);
            }
        }
        __syncthreads();
    }

    // epilogue: bias + softmax + scatter. lane holds col pair (c0, c0+1).
#pragma unroll
    for (int mi = 0; mi < 2; mi++) {
#pragma unroll
        for (int nt = 0; nt < 3; nt++) {
            int c0 = nt * 8 + (lane & 3) * 2;
            if (c0 >= 18) continue;
#pragma unroll
            for (int hrow = 0; hrow < 2; hrow++) {
                int r  = wid * 32 + mi * 16 + (lane >> 2) + hrow * 8;
                float v0 = acc[mi][nt][hrow * 2 + 0];
                float v1 = acc[mi][nt][hrow * 2 + 1];
                int pl  = lpix + r;
                int b   = pl / HH;
                int rem = pl - b * HH;
                if (c0 < 6) {
                    float l0 = v0 + bsm[c0];
                    float l1 = v1 + bsm[c0 + 1];
                    float mx = fmaxf(l0, l1);
                    float e0 = expf(l0 - mx), e1 = expf(l1 - mx);
                    float inv = 1.f / (e0 + e1);
                    int pos = c_posOff[l] + rem * 3 + (c0 >> 1);
                    size_t idx = ((size_t)b * TOT_POS + pos) * 2;
                    out_logit[idx]     = l0;
                    out_logit[idx + 1] = l1;
                    out_prob[idx]      = e0 * inv;
                    out_prob[idx + 1]  = e1 * inv;
                } else {
                    int bo = c0 - 6;
                    int a = bo >> 2, coord = bo & 3;
                    int pos = c_posOff[l] + rem * 3 + a;
                    size_t bidx = ((size_t)b * TOT_POS + pos) * 4 + coord;
                    out_box[bidx]     = v0 + bsm[c0];
                    out_box[bidx + 1] = v1 + bsm[c0 + 1];
                }
            }
        }
    }
}

// ---------------------------------------------------------------------------
extern "C" void kernel_launch(void* const* d_in, const int* in_sizes, int n_in,
                              void* d_out, int out_size)
{
    const float* p0 = (const float*)d_in[0];
    const float* p1 = (const float*)d_in[1];
    const float* p2 = (const float*)d_in[2];
    const float* p3 = (const float*)d_in[3];
    const float* p4 = (const float*)d_in[4];
    const float* w_share = (const float*)d_in[5];
    const float* b_share = (const float*)d_in[6];
    const float* w_cls   = (const float*)d_in[7];
    const float* b_cls   = (const float*)d_in[8];
    const float* w_box   = (const float*)d_in[9];
    const float* b_box   = (const float*)d_in[10];
    float* out = (float*)d_out;

    float* out_logit = out;
    float* out_prob  = out + (size_t)2 * TOT_POS * 2;
    float* out_box   = out + (size_t)4 * TOT_POS * 2;

    cudaFuncSetAttribute(conv_gemm_kernel,
                         cudaFuncAttributeMaxDynamicSharedMemorySize, SMEM_DYN);
    cudaFuncSetAttribute(heads_kernel,
                         cudaFuncAttributeMaxDynamicSharedMemorySize, H_SMEM);

    cvt_x_kernel<<<(TOTM * 64 + 255) / 256, 256>>>(p0, p1, p2, p3, p4);
    cvt_w_kernel<<<(512 * KTOT + 255) / 256, 256>>>(w_share);
    cvt_wh_kernel<<<1, 512>>>(w_cls, w_box);

    dim3 grid(1364, 2);
    conv_gemm_kernel<<<grid, 512, SMEM_DYN>>>(b_share);

    heads_kernel<<<1364, 128, H_SMEM>>>(b_cls, b_box,
                                        out_logit, out_prob, out_box);
}

// round 6
// speedup vs baseline: 6.8956x; 1.0770x over previous
#include <cuda_runtime.h>
#include <cuda_fp16.h>
#include <cstdint>
#include <cstddef>

// ============================================================================
// RPNHead: single-pass fp16 mma.sync implicit GEMM (K=2304), CTA 128x256,
// 8 warps / warp-tile 64x64, 4-stage cp.async, 1 sync per stage.
// fp16 s scratch; HMMA-based fused heads + softmax.
// ============================================================================

#define TOTM     174592
#define TOT_POS  261888
#define KTOT     2304            // 9 * 256
#define NSTAGE   72              // KTOT / 32

// conv smem: padded rows 32 fp16 + 8 pad = 80 bytes
#define A_TILE_B (128 * 80)
#define B_TILE_B (256 * 80)
#define STAGE_B  (A_TILE_B + B_TILE_B)   // 30720
#define SMEM_DYN (4 * STAGE_B)           // 122880

// heads smem layout (bytes)
#define HW_PITCH 1040
#define HS_PITCH 144
#define H_S0     25088
#define H_S1     43520
#define H_BIAS   61952
#define H_SMEM   62080

__device__ __align__(16) __half g_x16[(size_t)TOTM * 256];
__device__ __align__(16) __half g_wT [(size_t)512 * KTOT];
__device__ __align__(16) __half g_wh [24 * 512];
__device__ __align__(16) __half g_s16[(size_t)TOTM * 512];

// ---------------------------------------------------------------------------
__device__ __forceinline__ uint32_t smem_u32(const void* p) {
    uint32_t a;
    asm("{ .reg .u64 t; cvta.to.shared.u64 t, %1; cvt.u32.u64 %0, t; }"
        : "=r"(a) : "l"(p));
    return a;
}
__device__ __forceinline__ void cp_async16(uint32_t dst, const void* src, int sz) {
    asm volatile("cp.async.ca.shared.global [%0], [%1], 16, %2;"
                 :: "r"(dst), "l"(src), "r"(sz) : "memory");
}
__device__ __forceinline__ void cp_commit() {
    asm volatile("cp.async.commit_group;" ::: "memory");
}
__device__ __forceinline__ void cp_wait1() {
    asm volatile("cp.async.wait_group 1;" ::: "memory");
}
__device__ __forceinline__ void cp_wait2() {
    asm volatile("cp.async.wait_group 2;" ::: "memory");
}
__device__ __forceinline__ void ldm_x4(uint32_t* r, uint32_t addr) {
    asm volatile("ldmatrix.sync.aligned.m8n8.x4.shared.b16 {%0,%1,%2,%3}, [%4];"
                 : "=r"(r[0]), "=r"(r[1]), "=r"(r[2]), "=r"(r[3]) : "r"(addr));
}
__device__ __forceinline__ void ldm_x2(uint32_t* r, uint32_t addr) {
    asm volatile("ldmatrix.sync.aligned.m8n8.x2.shared.b16 {%0,%1}, [%2];"
                 : "=r"(r[0]), "=r"(r[1]) : "r"(addr));
}
__device__ __forceinline__ void mma16816(float* c, const uint32_t* a,
                                         uint32_t b0, uint32_t b1) {
    asm volatile(
        "mma.sync.aligned.m16n8k16.row.col.f32.f16.f16.f32 "
        "{%0,%1,%2,%3}, {%4,%5,%6,%7}, {%8,%9}, {%0,%1,%2,%3};"
        : "+f"(c[0]), "+f"(c[1]), "+f"(c[2]), "+f"(c[3])
        : "r"(a[0]), "r"(a[1]), "r"(a[2]), "r"(a[3]), "r"(b0), "r"(b1));
}

__device__ __forceinline__ int lvl_of_blk(int mb) {
    return (mb >= 1360) ? 4 : (mb >= 1344) ? 3 : (mb >= 1280) ? 2
         : (mb >= 1024) ? 1 : 0;
}
__constant__ int c_H[5]      = {256, 128, 64, 32, 16};
__constant__ int c_pixB[5]   = {0, 131072, 163840, 172032, 174080};
__constant__ int c_blkB[5]   = {0, 1024, 1280, 1344, 1360};
__constant__ int c_posOff[5] = {0, 196608, 245760, 258048, 261120};

// ---------------------------------------------------------------------------
// conversion kernels
// ---------------------------------------------------------------------------
__global__ __launch_bounds__(256)
void cvt_x_kernel(const float* __restrict__ x0, const float* __restrict__ x1,
                  const float* __restrict__ x2, const float* __restrict__ x3,
                  const float* __restrict__ x4)
{
    int i = blockIdx.x * 256 + threadIdx.x;
    if (i >= TOTM * 64) return;
    int l = (i >= 174080 * 64) ? 4 : (i >= 172032 * 64) ? 3
          : (i >= 163840 * 64) ? 2 : (i >= 131072 * 64) ? 1 : 0;
    const float* xs[5] = {x0, x1, x2, x3, x4};
    int li = i - c_pixB[l] * 64;
    float4 v = reinterpret_cast<const float4*>(xs[l])[li];
    __half2 h01 = __floats2half2_rn(v.x, v.y);
    __half2 h23 = __floats2half2_rn(v.z, v.w);
    *reinterpret_cast<uint2*>(g_x16 + (size_t)i * 4) =
        make_uint2(*reinterpret_cast<uint32_t*>(&h01),
                   *reinterpret_cast<uint32_t*>(&h23));
}

__global__ __launch_bounds__(256)
void cvt_w_kernel(const float* __restrict__ wsh)
{
    int i = blockIdx.x * 256 + threadIdx.x;
    if (i >= 512 * KTOT) return;
    int n = i / KTOT, k = i - n * KTOT;
    g_wT[(size_t)n * KTOT + k] = __float2half_rn(wsh[(size_t)k * 512 + n]);
}

__global__ __launch_bounds__(512)
void cvt_wh_kernel(const float* __restrict__ wcls, const float* __restrict__ wbox)
{
    int c = threadIdx.x;
#pragma unroll
    for (int o = 0; o < 24; o++) {
        float v = 0.f;
        if (o < 6)       v = wcls[(size_t)c * 6 + o];
        else if (o < 18) v = wbox[(size_t)c * 12 + (o - 6)];
        g_wh[o * 512 + c] = __float2half_rn(v);
    }
}

// ---------------------------------------------------------------------------
// conv3x3 + bias + relu. grid (1364, 2), block 256 (8 warps: 2m x 4n),
// warp tile 64x64, 4-stage pipeline, one __syncthreads per stage.
// ---------------------------------------------------------------------------
__global__ __launch_bounds__(256, 1)
void conv_gemm_kernel(const float* __restrict__ bsh)
{
    extern __shared__ __align__(16) char smem[];
    const uint32_t su = smem_u32(smem);

    const int tid  = threadIdx.x;
    const int wid  = tid >> 5;
    const int lane = tid & 31;
    const int mb   = blockIdx.x;
    const int n0   = blockIdx.y * 256;

    const int l    = lvl_of_blk(mb);
    const int H    = c_H[l];
    const int HH   = H * H;
    const int pixB = c_pixB[l] + (mb - c_blkB[l]) * 128;

    // A: 512 vecs (128 rows x 4 segs) -> 2/thread
    int pb[2], phh[2], pww[2], a_rowi[2], a_segi[2];
#pragma unroll
    for (int i = 0; i < 2; i++) {
        int v = tid + i * 256;
        a_rowi[i] = v >> 2; a_segi[i] = v & 3;
        int p = (pixB - c_pixB[l]) + a_rowi[i];
        pb[i] = p / HH; int rem = p - pb[i] * HH;
        phh[i] = rem / H; pww[i] = rem - phh[i] * H;
    }
    const size_t xlevel = (size_t)c_pixB[l] * 256;

    auto issue = [&](int s, int buf) {
        const uint32_t sb = su + buf * STAGE_B;
        int k0 = s * 32;
        int tap = k0 >> 8;
        int kin = k0 & 255;
        int dr = tap / 3 - 1, dc = tap - (tap / 3) * 3 - 1;
#pragma unroll
        for (int i = 0; i < 2; i++) {
            int hh = phh[i] + dr, ww = pww[i] + dc;
            bool ok = ((unsigned)hh < (unsigned)H) && ((unsigned)ww < (unsigned)H);
            const void* src = ok
                ? (const void*)(g_x16 + xlevel
                    + (((size_t)(pb[i] * H + hh)) * H + ww) * 256 + kin + a_segi[i] * 8)
                : (const void*)g_x16;
            cp_async16(sb + a_rowi[i] * 80 + a_segi[i] * 16, src, ok ? 16 : 0);
        }
        // B: 1024 vecs (256 rows x 4 segs) -> 4/thread
#pragma unroll
        for (int i = 0; i < 4; i++) {
            int v = tid + i * 256;
            int row = v >> 2, sg = v & 3;
            const void* src = g_wT + (size_t)(n0 + row) * KTOT + k0 + sg * 8;
            cp_async16(sb + A_TILE_B + row * 80 + sg * 16, src, 16);
        }
        cp_commit();
    };

    const int wm = wid >> 2;     // 0..1 -> 64-row group
    const int wn = wid & 3;      // 0..3 -> 64-col group

    float acc[4][8][4];
#pragma unroll
    for (int mi = 0; mi < 4; mi++)
#pragma unroll
        for (int j = 0; j < 8; j++)
#pragma unroll
            for (int e = 0; e < 4; e++) acc[mi][j][e] = 0.f;

    const int la_row = (lane & 15);
    const int la_k   = ((lane >> 4) << 3);
    const int lb_row = ((lane >> 4) << 3) + (lane & 7);
    const int lb_k   = ((lane >> 3) & 1) << 3;

    issue(0, 0);
    issue(1, 1);
    issue(2, 2);
#pragma unroll 1
    for (int s = 0; s < NSTAGE; s++) {
        const int buf = s & 3;
        cp_wait2();
        __syncthreads();
        if (s + 3 < NSTAGE) issue(s + 3, (s + 3) & 3);
        else                cp_commit();

        const uint32_t sA = su + buf * STAGE_B;
        const uint32_t sB = sA + A_TILE_B;
#pragma unroll
        for (int kk = 0; kk < 32; kk += 16) {
            uint32_t af[4][4];
#pragma unroll
            for (int mi = 0; mi < 4; mi++)
                ldm_x4(af[mi], sA + (wm * 64 + mi * 16 + la_row) * 80
                                  + (kk + la_k) * 2);
            uint32_t bf[4][4];
#pragma unroll
            for (int q = 0; q < 4; q++)
                ldm_x4(bf[q], sB + (wn * 64 + q * 16 + lb_row) * 80
                                 + (kk + lb_k) * 2);
#pragma unroll
            for (int mi = 0; mi < 4; mi++)
#pragma unroll
                for (int j = 0; j < 8; j++)
                    mma16816(acc[mi][j], af[mi],
                             bf[j >> 1][(j & 1) * 2], bf[j >> 1][(j & 1) * 2 + 1]);
        }
    }
    __syncthreads();

    // epilogue: bias + relu -> fp16, stage through smem, coalesced store
    __half* ep = reinterpret_cast<__half*>(smem);   // [128][256]
    const int qr = lane >> 2;
    const int qc = (lane & 3) * 2;
#pragma unroll
    for (int mi = 0; mi < 4; mi++) {
#pragma unroll
        for (int j = 0; j < 8; j++) {
            int col = wn * 64 + j * 8 + qc;
            float b0 = __ldg(bsh + n0 + col);
            float b1 = __ldg(bsh + n0 + col + 1);
            int r0 = wm * 64 + mi * 16 + qr;
            float v0 = fmaxf(acc[mi][j][0] + b0, 0.f);
            float v1 = fmaxf(acc[mi][j][1] + b1, 0.f);
            float v2 = fmaxf(acc[mi][j][2] + b0, 0.f);
            float v3 = fmaxf(acc[mi][j][3] + b1, 0.f);
            *reinterpret_cast<__half2*>(ep + r0 * 256 + col)       = __floats2half2_rn(v0, v1);
            *reinterpret_cast<__half2*>(ep + (r0 + 8) * 256 + col) = __floats2half2_rn(v2, v3);
        }
    }
    __syncthreads();
#pragma unroll
    for (int t = 0; t < 16; t++) {
        int idx = t * 256 + tid;
        int row = idx >> 5, sg = idx & 31;
        uint4 v = *reinterpret_cast<const uint4*>(ep + row * 256 + sg * 8);
        *reinterpret_cast<uint4*>(g_s16 + (size_t)(pixB + row) * 512
                                  + n0 + sg * 8) = v;
    }
}

// ---------------------------------------------------------------------------
// heads: s[128x512] @ whead^T[24x512] via HMMA, fused softmax + scatter.
// grid 1364, block 128 (4 warps, warp tile 32x24).
// ---------------------------------------------------------------------------
__global__ __launch_bounds__(128)
void heads_kernel(const float* __restrict__ bcls, const float* __restrict__ bbox,
                  float* __restrict__ out_logit, float* __restrict__ out_prob,
                  float* __restrict__ out_box)
{
    extern __shared__ __align__(16) char smem[];
    const uint32_t su = smem_u32(smem);
    float* bsm = reinterpret_cast<float*>(smem + H_BIAS);

    const int tid  = threadIdx.x;
    const int wid  = tid >> 5;
    const int lane = tid & 31;
    const int mb   = blockIdx.x;

    const int l    = lvl_of_blk(mb);
    const int H    = c_H[l];
    const int HH   = H * H;
    const int lpix = (mb - c_blkB[l]) * 128;
    const int gpix = c_pixB[l] + lpix;

    for (int i = tid; i < 24 * 64; i += 128) {
        int r = i >> 6, sg = i & 63;
        *reinterpret_cast<uint4*>(smem + r * HW_PITCH + sg * 16) =
            *reinterpret_cast<const uint4*>(g_wh + r * 512 + sg * 8);
    }
    if (tid < 6)       bsm[tid] = bcls[tid];
    else if (tid < 18) bsm[tid] = bbox[tid - 6];

    auto sload = [&](int ck, int buf) {
#pragma unroll
        for (int j = 0; j < 8; j++) {
            int v = tid + j * 128;
            int row = v >> 3, sg = v & 7;
            cp_async16(su + (buf ? H_S1 : H_S0) + row * HS_PITCH + sg * 16,
                       g_s16 + (size_t)(gpix + row) * 512 + ck * 64 + sg * 8, 16);
        }
        cp_commit();
    };

    float acc[2][3][4];
#pragma unroll
    for (int mi = 0; mi < 2; mi++)
#pragma unroll
        for (int nt = 0; nt < 3; nt++)
#pragma unroll
            for (int e = 0; e < 4; e++) acc[mi][nt][e] = 0.f;

    sload(0, 0);
    __syncthreads();

#pragma unroll 1
    for (int ck = 0; ck < 8; ck++) {
        const int buf = ck & 1;
        if (ck + 1 < 8) sload(ck + 1, buf ^ 1);
        else            cp_commit();
        cp_wait1();
        __syncthreads();

        const uint32_t sb = su + (buf ? H_S1 : H_S0);
#pragma unroll
        for (int k16 = 0; k16 < 4; k16++) {
            uint32_t af[2][4];
#pragma unroll
            for (int mi = 0; mi < 2; mi++)
                ldm_x4(af[mi], sb + (wid * 32 + mi * 16 + (lane & 15)) * HS_PITCH
                                  + (k16 * 16 + ((lane >> 4) << 3)) * 2);
            int kcol = (ck * 64 + k16 * 16 + (((lane >> 3) & 1) << 3)) * 2;
            uint32_t b01[4], b2[2];
            ldm_x4(b01, su + (((lane >> 4) << 3) + (lane & 7)) * HW_PITCH + kcol);
            ldm_x2(b2,  su + (16 + (lane & 7)) * HW_PITCH + kcol);
#pragma unroll
            for (int mi = 0; mi < 2; mi++) {
                mma16816(acc[mi][0], af[mi], b01[0], b01[1]);
                mma16816(acc[mi][1], af[mi], b01[2], b01[3]);
                mma16816(acc[mi][2], af[mi], b2[0],  b2[1]);
            }
        }
        __syncthreads();
    }

#pragma unroll
    for (int mi = 0; mi < 2; mi++) {
#pragma unroll
        for (int nt = 0; nt < 3; nt++) {
            int c0 = nt * 8 + (lane & 3) * 2;
            if (c0 >= 18) continue;
#pragma unroll
            for (int hrow = 0; hrow < 2; hrow++) {
                int r  = wid * 32 + mi * 16 + (lane >> 2) + hrow * 8;
                float v0 = acc[mi][nt][hrow * 2 + 0];
                float v1 = acc[mi][nt][hrow * 2 + 1];
                int pl  = lpix + r;
                int b   = pl / HH;
                int rem = pl - b * HH;
                if (c0 < 6) {
                    float l0 = v0 + bsm[c0];
                    float l1 = v1 + bsm[c0 + 1];
                    float mx = fmaxf(l0, l1);
                    float e0 = expf(l0 - mx), e1 = expf(l1 - mx);
                    float inv = 1.f / (e0 + e1);
                    int pos = c_posOff[l] + rem * 3 + (c0 >> 1);
                    size_t idx = ((size_t)b * TOT_POS + pos) * 2;
                    out_logit[idx]     = l0;
                    out_logit[idx + 1] = l1;
                    out_prob[idx]      = e0 * inv;
                    out_prob[idx + 1]  = e1 * inv;
                } else {
                    int bo = c0 - 6;
                    int a = bo >> 2, coord = bo & 3;
                    int pos = c_posOff[l] + rem * 3 + a;
                    size_t bidx = ((size_t)b * TOT_POS + pos) * 4 + coord;
                    out_box[bidx]     = v0 + bsm[c0];
                    out_box[bidx + 1] = v1 + bsm[c0 + 1];
                }
            }
        }
    }
}

// ---------------------------------------------------------------------------
extern "C" void kernel_launch(void* const* d_in, const int* in_sizes, int n_in,
                              void* d_out, int out_size)
{
    const float* p0 = (const float*)d_in[0];
    const float* p1 = (const float*)d_in[1];
    const float* p2 = (const float*)d_in[2];
    const float* p3 = (const float*)d_in[3];
    const float* p4 = (const float*)d_in[4];
    const float* w_share = (const float*)d_in[5];
    const float* b_share = (const float*)d_in[6];
    const float* w_cls   = (const float*)d_in[7];
    const float* b_cls   = (const float*)d_in[8];
    const float* w_box   = (const float*)d_in[9];
    const float* b_box   = (const float*)d_in[10];
    float* out = (float*)d_out;

    float* out_logit = out;
    float* out_prob  = out + (size_t)2 * TOT_POS * 2;
    float* out_box   = out + (size_t)4 * TOT_POS * 2;

    cudaFuncSetAttribute(conv_gemm_kernel,
                         cudaFuncAttributeMaxDynamicSharedMemorySize, SMEM_DYN);
    cudaFuncSetAttribute(heads_kernel,
                         cudaFuncAttributeMaxDynamicSharedMemorySize, H_SMEM);

    cvt_x_kernel<<<(TOTM * 64 + 255) / 256, 256>>>(p0, p1, p2, p3, p4);
    cvt_w_kernel<<<(512 * KTOT + 255) / 256, 256>>>(w_share);
    cvt_wh_kernel<<<1, 512>>>(w_cls, w_box);

    dim3 grid(1364, 2);
    conv_gemm_kernel<<<grid, 256, SMEM_DYN>>>(b_share);

    heads_kernel<<<1364, 128, H_SMEM>>>(b_cls, b_box,
                                        out_logit, out_prob, out_box);
}

// round 7
// speedup vs baseline: 8.4337x; 1.2231x over previous
#include <cuda_runtime.h>
#include <cuda_fp16.h>
#include <cstdint>
#include <cstddef>

// ============================================================================
// RPNHead: single-pass fp16 mma.sync implicit GEMM (K=2304), CTA 128x256,
// 8 warps / warp-tile 64x64, K-stage 64, 3-stage cp.async, 1 sync per stage,
// register-fragment double buffering. fp16 s scratch; HMMA fused heads.
// ============================================================================

#define TOTM     174592
#define TOT_POS  261888
#define KTOT     2304            // 9 * 256
#define NSTAGE   36              // KTOT / 64

// conv smem: rows of 64 fp16 = 128B + 16B pad = 144B pitch
#define ROW_P    144
#define A_TILE_B (128 * ROW_P)   // 18432
#define B_TILE_B (256 * ROW_P)   // 36864
#define STAGE_B  (A_TILE_B + B_TILE_B)   // 55296
#define SMEM_DYN (3 * STAGE_B)           // 165888

// heads smem layout (bytes)
#define HW_PITCH 1040
#define HS_PITCH 144
#define H_S0     25088
#define H_S1     43520
#define H_BIAS   61952
#define H_SMEM   62080

__device__ __align__(16) __half g_x16[(size_t)TOTM * 256];
__device__ __align__(16) __half g_wT [(size_t)512 * KTOT];
__device__ __align__(16) __half g_wh [24 * 512];
__device__ __align__(16) __half g_s16[(size_t)TOTM * 512];

// ---------------------------------------------------------------------------
__device__ __forceinline__ uint32_t smem_u32(const void* p) {
    uint32_t a;
    asm("{ .reg .u64 t; cvta.to.shared.u64 t, %1; cvt.u32.u64 %0, t; }"
        : "=r"(a) : "l"(p));
    return a;
}
__device__ __forceinline__ void cp_async16(uint32_t dst, const void* src, int sz) {
    asm volatile("cp.async.ca.shared.global [%0], [%1], 16, %2;"
                 :: "r"(dst), "l"(src), "r"(sz) : "memory");
}
__device__ __forceinline__ void cp_commit() {
    asm volatile("cp.async.commit_group;" ::: "memory");
}
__device__ __forceinline__ void cp_wait1() {
    asm volatile("cp.async.wait_group 1;" ::: "memory");
}
__device__ __forceinline__ void ldm_x4(uint32_t* r, uint32_t addr) {
    asm volatile("ldmatrix.sync.aligned.m8n8.x4.shared.b16 {%0,%1,%2,%3}, [%4];"
                 : "=r"(r[0]), "=r"(r[1]), "=r"(r[2]), "=r"(r[3]) : "r"(addr));
}
__device__ __forceinline__ void ldm_x2(uint32_t* r, uint32_t addr) {
    asm volatile("ldmatrix.sync.aligned.m8n8.x2.shared.b16 {%0,%1}, [%2];"
                 : "=r"(r[0]), "=r"(r[1]) : "r"(addr));
}
__device__ __forceinline__ void mma16816(float* c, const uint32_t* a,
                                         uint32_t b0, uint32_t b1) {
    asm volatile(
        "mma.sync.aligned.m16n8k16.row.col.f32.f16.f16.f32 "
        "{%0,%1,%2,%3}, {%4,%5,%6,%7}, {%8,%9}, {%0,%1,%2,%3};"
        : "+f"(c[0]), "+f"(c[1]), "+f"(c[2]), "+f"(c[3])
        : "r"(a[0]), "r"(a[1]), "r"(a[2]), "r"(a[3]), "r"(b0), "r"(b1));
}

__device__ __forceinline__ int lvl_of_blk(int mb) {
    return (mb >= 1360) ? 4 : (mb >= 1344) ? 3 : (mb >= 1280) ? 2
         : (mb >= 1024) ? 1 : 0;
}
__constant__ int c_H[5]      = {256, 128, 64, 32, 16};
__constant__ int c_pixB[5]   = {0, 131072, 163840, 172032, 174080};
__constant__ int c_blkB[5]   = {0, 1024, 1280, 1344, 1360};
__constant__ int c_posOff[5] = {0, 196608, 245760, 258048, 261120};

// ---------------------------------------------------------------------------
// conversion kernels
// ---------------------------------------------------------------------------
__global__ __launch_bounds__(256)
void cvt_x_kernel(const float* __restrict__ x0, const float* __restrict__ x1,
                  const float* __restrict__ x2, const float* __restrict__ x3,
                  const float* __restrict__ x4)
{
    int i = blockIdx.x * 256 + threadIdx.x;
    if (i >= TOTM * 64) return;
    int l = (i >= 174080 * 64) ? 4 : (i >= 172032 * 64) ? 3
          : (i >= 163840 * 64) ? 2 : (i >= 131072 * 64) ? 1 : 0;
    const float* xs[5] = {x0, x1, x2, x3, x4};
    int li = i - c_pixB[l] * 64;
    float4 v = reinterpret_cast<const float4*>(xs[l])[li];
    __half2 h01 = __floats2half2_rn(v.x, v.y);
    __half2 h23 = __floats2half2_rn(v.z, v.w);
    *reinterpret_cast<uint2*>(g_x16 + (size_t)i * 4) =
        make_uint2(*reinterpret_cast<uint32_t*>(&h01),
                   *reinterpret_cast<uint32_t*>(&h23));
}

__global__ __launch_bounds__(256)
void cvt_w_kernel(const float* __restrict__ wsh)
{
    int i = blockIdx.x * 256 + threadIdx.x;
    if (i >= 512 * KTOT) return;
    int n = i / KTOT, k = i - n * KTOT;
    g_wT[(size_t)n * KTOT + k] = __float2half_rn(wsh[(size_t)k * 512 + n]);
}

__global__ __launch_bounds__(512)
void cvt_wh_kernel(const float* __restrict__ wcls, const float* __restrict__ wbox)
{
    int c = threadIdx.x;
#pragma unroll
    for (int o = 0; o < 24; o++) {
        float v = 0.f;
        if (o < 6)       v = wcls[(size_t)c * 6 + o];
        else if (o < 18) v = wbox[(size_t)c * 12 + (o - 6)];
        g_wh[o * 512 + c] = __float2half_rn(v);
    }
}

// ---------------------------------------------------------------------------
// conv3x3 + bias + relu. grid (1364, 2), block 256 (8 warps: 2m x 4n),
// warp tile 64x64, K-stage 64, 3 buffers, 1 sync/stage, frag double-buffer.
// ---------------------------------------------------------------------------
__global__ __launch_bounds__(256, 1)
void conv_gemm_kernel(const float* __restrict__ bsh)
{
    extern __shared__ __align__(16) char smem[];
    const uint32_t su = smem_u32(smem);

    const int tid  = threadIdx.x;
    const int wid  = tid >> 5;
    const int lane = tid & 31;
    const int mb   = blockIdx.x;
    const int n0   = blockIdx.y * 256;

    const int l    = lvl_of_blk(mb);
    const int H    = c_H[l];
    const int HH   = H * H;
    const int pixB = c_pixB[l] + (mb - c_blkB[l]) * 128;

    // A: 1024 vecs (128 rows x 8 segs of 16B) -> 4/thread, rows tid>>3 + 32i
    const int a_seg = tid & 7;
    const int a_r0  = tid >> 3;
    int pb[4], phh[4], pww[4];
#pragma unroll
    for (int i = 0; i < 4; i++) {
        int p = (pixB - c_pixB[l]) + a_r0 + i * 32;
        pb[i] = p / HH; int rem = p - pb[i] * HH;
        phh[i] = rem / H; pww[i] = rem - phh[i] * H;
    }
    const size_t xlevel = (size_t)c_pixB[l] * 256;

    auto issue = [&](int s, int buf) {
        const uint32_t sb = su + buf * STAGE_B;
        int k0 = s * 64;
        int tap = k0 >> 8;
        int kin = k0 & 255;
        int dr = tap / 3 - 1, dc = tap - (tap / 3) * 3 - 1;
#pragma unroll
        for (int i = 0; i < 4; i++) {
            int hh = phh[i] + dr, ww = pww[i] + dc;
            bool ok = ((unsigned)hh < (unsigned)H) && ((unsigned)ww < (unsigned)H);
            const void* src = ok
                ? (const void*)(g_x16 + xlevel
                    + (((size_t)(pb[i] * H + hh)) * H + ww) * 256 + kin + a_seg * 8)
                : (const void*)g_x16;
            cp_async16(sb + (a_r0 + i * 32) * ROW_P + a_seg * 16, src, ok ? 16 : 0);
        }
        // B: 2048 vecs (256 rows x 8 segs) -> 8/thread
#pragma unroll
        for (int i = 0; i < 8; i++) {
            int row = a_r0 + i * 32;
            const void* src = g_wT + (size_t)(n0 + row) * KTOT + k0 + a_seg * 8;
            cp_async16(sb + A_TILE_B + row * ROW_P + a_seg * 16, src, 16);
        }
        cp_commit();
    };

    const int wm = wid >> 2;     // 0..1 -> 64-row group
    const int wn = wid & 3;      // 0..3 -> 64-col group

    float acc[4][8][4];
#pragma unroll
    for (int mi = 0; mi < 4; mi++)
#pragma unroll
        for (int j = 0; j < 8; j++)
#pragma unroll
            for (int e = 0; e < 4; e++) acc[mi][j][e] = 0.f;

    const int la_row = (lane & 15);
    const int la_k   = ((lane >> 4) << 3);
    const int lb_row = ((lane >> 4) << 3) + (lane & 7);
    const int lb_k   = ((lane >> 3) & 1) << 3;

    issue(0, 0);
    issue(1, 1);
#pragma unroll 1
    for (int s = 0; s < NSTAGE; s++) {
        const int buf = s % 3;
        cp_wait1();
        __syncthreads();
        if (s + 2 < NSTAGE) issue(s + 2, (s + 2) % 3);
        else                cp_commit();

        const uint32_t sA = su + buf * STAGE_B;
        const uint32_t sB = sA + A_TILE_B;

        uint32_t af[2][4][4], bf[2][4][4];
        // preload k16 = 0
#pragma unroll
        for (int mi = 0; mi < 4; mi++)
            ldm_x4(af[0][mi], sA + (wm * 64 + mi * 16 + la_row) * ROW_P + la_k * 2);
#pragma unroll
        for (int q = 0; q < 4; q++)
            ldm_x4(bf[0][q], sB + (wn * 64 + q * 16 + lb_row) * ROW_P + lb_k * 2);

#pragma unroll
        for (int k16 = 0; k16 < 4; k16++) {
            const int cur = k16 & 1;
            if (k16 < 3) {
                const int kk = (k16 + 1) * 16;
#pragma unroll
                for (int mi = 0; mi < 4; mi++)
                    ldm_x4(af[cur ^ 1][mi],
                           sA + (wm * 64 + mi * 16 + la_row) * ROW_P + (kk + la_k) * 2);
#pragma unroll
                for (int q = 0; q < 4; q++)
                    ldm_x4(bf[cur ^ 1][q],
                           sB + (wn * 64 + q * 16 + lb_row) * ROW_P + (kk + lb_k) * 2);
            }
#pragma unroll
            for (int mi = 0; mi < 4; mi++)
#pragma unroll
                for (int j = 0; j < 8; j++)
                    mma16816(acc[mi][j], af[cur][mi],
                             bf[cur][j >> 1][(j & 1) * 2],
                             bf[cur][j >> 1][(j & 1) * 2 + 1]);
        }
    }
    __syncthreads();

    // epilogue: bias + relu -> fp16, stage through smem, coalesced store
    __half* ep = reinterpret_cast<__half*>(smem);   // [128][256]
    const int qr = lane >> 2;
    const int qc = (lane & 3) * 2;
#pragma unroll
    for (int mi = 0; mi < 4; mi++) {
#pragma unroll
        for (int j = 0; j < 8; j++) {
            int col = wn * 64 + j * 8 + qc;
            float b0 = __ldg(bsh + n0 + col);
            float b1 = __ldg(bsh + n0 + col + 1);
            int r0 = wm * 64 + mi * 16 + qr;
            float v0 = fmaxf(acc[mi][j][0] + b0, 0.f);
            float v1 = fmaxf(acc[mi][j][1] + b1, 0.f);
            float v2 = fmaxf(acc[mi][j][2] + b0, 0.f);
            float v3 = fmaxf(acc[mi][j][3] + b1, 0.f);
            *reinterpret_cast<__half2*>(ep + r0 * 256 + col)       = __floats2half2_rn(v0, v1);
            *reinterpret_cast<__half2*>(ep + (r0 + 8) * 256 + col) = __floats2half2_rn(v2, v3);
        }
    }
    __syncthreads();
#pragma unroll
    for (int t = 0; t < 16; t++) {
        int idx = t * 256 + tid;
        int row = idx >> 5, sg = idx & 31;
        uint4 v = *reinterpret_cast<const uint4*>(ep + row * 256 + sg * 8);
        *reinterpret_cast<uint4*>(g_s16 + (size_t)(pixB + row) * 512
                                  + n0 + sg * 8) = v;
    }
}

// ---------------------------------------------------------------------------
// heads: s[128x512] @ whead^T[24x512] via HMMA, fused softmax + scatter.
// ---------------------------------------------------------------------------
__global__ __launch_bounds__(128)
void heads_kernel(const float* __restrict__ bcls, const float* __restrict__ bbox,
                  float* __restrict__ out_logit, float* __restrict__ out_prob,
                  float* __restrict__ out_box)
{
    extern __shared__ __align__(16) char smem[];
    const uint32_t su = smem_u32(smem);
    float* bsm = reinterpret_cast<float*>(smem + H_BIAS);

    const int tid  = threadIdx.x;
    const int wid  = tid >> 5;
    const int lane = tid & 31;
    const int mb   = blockIdx.x;

    const int l    = lvl_of_blk(mb);
    const int H    = c_H[l];
    const int HH   = H * H;
    const int lpix = (mb - c_blkB[l]) * 128;
    const int gpix = c_pixB[l] + lpix;

    for (int i = tid; i < 24 * 64; i += 128) {
        int r = i >> 6, sg = i & 63;
        *reinterpret_cast<uint4*>(smem + r * HW_PITCH + sg * 16) =
            *reinterpret_cast<const uint4*>(g_wh + r * 512 + sg * 8);
    }
    if (tid < 6)       bsm[tid] = bcls[tid];
    else if (tid < 18) bsm[tid] = bbox[tid - 6];

    auto sload = [&](int ck, int buf) {
#pragma unroll
        for (int j = 0; j < 8; j++) {
            int v = tid + j * 128;
            int row = v >> 3, sg = v & 7;
            cp_async16(su + (buf ? H_S1 : H_S0) + row * HS_PITCH + sg * 16,
                       g_s16 + (size_t)(gpix + row) * 512 + ck * 64 + sg * 8, 16);
        }
        cp_commit();
    };

    float acc[2][3][4];
#pragma unroll
    for (int mi = 0; mi < 2; mi++)
#pragma unroll
        for (int nt = 0; nt < 3; nt++)
#pragma unroll
            for (int e = 0; e < 4; e++) acc[mi][nt][e] = 0.f;

    sload(0, 0);
    __syncthreads();

#pragma unroll 1
    for (int ck = 0; ck < 8; ck++) {
        const int buf = ck & 1;
        if (ck + 1 < 8) sload(ck + 1, buf ^ 1);
        else            cp_commit();
        cp_wait1();
        __syncthreads();

        const uint32_t sb = su + (buf ? H_S1 : H_S0);
#pragma unroll
        for (int k16 = 0; k16 < 4; k16++) {
            uint32_t af[2][4];
#pragma unroll
            for (int mi = 0; mi < 2; mi++)
                ldm_x4(af[mi], sb + (wid * 32 + mi * 16 + (lane & 15)) * HS_PITCH
                                  + (k16 * 16 + ((lane >> 4) << 3)) * 2);
            int kcol = (ck * 64 + k16 * 16 + (((lane >> 3) & 1) << 3)) * 2;
            uint32_t b01[4], b2[2];
            ldm_x4(b01, su + (((lane >> 4) << 3) + (lane & 7)) * HW_PITCH + kcol);
            ldm_x2(b2,  su + (16 + (lane & 7)) * HW_PITCH + kcol);
#pragma unroll
            for (int mi = 0; mi < 2; mi++) {
                mma16816(acc[mi][0], af[mi], b01[0], b01[1]);
                mma16816(acc[mi][1], af[mi], b01[2], b01[3]);
                mma16816(acc[mi][2], af[mi], b2[0],  b2[1]);
            }
        }
        __syncthreads();
    }

#pragma unroll
    for (int mi = 0; mi < 2; mi++) {
#pragma unroll
        for (int nt = 0; nt < 3; nt++) {
            int c0 = nt * 8 + (lane & 3) * 2;
            if (c0 >= 18) continue;
#pragma unroll
            for (int hrow = 0; hrow < 2; hrow++) {
                int r  = wid * 32 + mi * 16 + (lane >> 2) + hrow * 8;
                float v0 = acc[mi][nt][hrow * 2 + 0];
                float v1 = acc[mi][nt][hrow * 2 + 1];
                int pl  = lpix + r;
                int b   = pl / HH;
                int rem = pl - b * HH;
                if (c0 < 6) {
                    float l0 = v0 + bsm[c0];
                    float l1 = v1 + bsm[c0 + 1];
                    float mx = fmaxf(l0, l1);
                    float e0 = expf(l0 - mx), e1 = expf(l1 - mx);
                    float inv = 1.f / (e0 + e1);
                    int pos = c_posOff[l] + rem * 3 + (c0 >> 1);
                    size_t idx = ((size_t)b * TOT_POS + pos) * 2;
                    out_logit[idx]     = l0;
                    out_logit[idx + 1] = l1;
                    out_prob[idx]      = e0 * inv;
                    out_prob[idx + 1]  = e1 * inv;
                } else {
                    int bo = c0 - 6;
                    int a = bo >> 2, coord = bo & 3;
                    int pos = c_posOff[l] + rem * 3 + a;
                    size_t bidx = ((size_t)b * TOT_POS + pos) * 4 + coord;
                    out_box[bidx]     = v0 + bsm[c0];
                    out_box[bidx + 1] = v1 + bsm[c0 + 1];
                }
            }
        }
    }
}

// ---------------------------------------------------------------------------
extern "C" void kernel_launch(void* const* d_in, const int* in_sizes, int n_in,
                              void* d_out, int out_size)
{
    const float* p0 = (const float*)d_in[0];
    const float* p1 = (const float*)d_in[1];
    const float* p2 = (const float*)d_in[2];
    const float* p3 = (const float*)d_in[3];
    const float* p4 = (const float*)d_in[4];
    const float* w_share = (const float*)d_in[5];
    const float* b_share = (const float*)d_in[6];
    const float* w_cls   = (const float*)d_in[7];
    const float* b_cls   = (const float*)d_in[8];
    const float* w_box   = (const float*)d_in[9];
    const float* b_box   = (const float*)d_in[10];
    float* out = (float*)d_out;

    float* out_logit = out;
    float* out_prob  = out + (size_t)2 * TOT_POS * 2;
    float* out_box   = out + (size_t)4 * TOT_POS * 2;

    cudaFuncSetAttribute(conv_gemm_kernel,
                         cudaFuncAttributeMaxDynamicSharedMemorySize, SMEM_DYN);
    cudaFuncSetAttribute(heads_kernel,
                         cudaFuncAttributeMaxDynamicSharedMemorySize, H_SMEM);

    cvt_x_kernel<<<(TOTM * 64 + 255) / 256, 256>>>(p0, p1, p2, p3, p4);
    cvt_w_kernel<<<(512 * KTOT + 255) / 256, 256>>>(w_share);
    cvt_wh_kernel<<<1, 512>>>(w_cls, w_box);

    dim3 grid(1364, 2);
    conv_gemm_kernel<<<grid, 256, SMEM_DYN>>>(b_share);

    heads_kernel<<<1364, 128, H_SMEM>>>(b_cls, b_box,
                                        out_logit, out_prob, out_box);
}